// round 1
// baseline (speedup 1.0000x reference)
#include <cuda_runtime.h>
#include <math.h>

#define B_    2
#define C_    1024
#define N_    80
#define D_    3074
#define TD_   9222
#define DFF_  2048
#define OUTD_ 1026
#define M_    160     // B_*N_
#define REFINE_ 3

// ---------------- scratch (module-static device memory, no runtime alloc) ----
__device__ float g_preq  [M_*C_];
__device__ float g_firstq[M_*C_];
__device__ float g_pe    [N_*D_];
__device__ float g_curr  [M_*2];
__device__ int   g_firstal[M_*2];
__device__ float g_tokens[M_*D_];
__device__ float g_qkv   [M_*TD_];
__device__ float g_av    [M_*D_];
__device__ float g_aproj [M_*D_];
__device__ float g_x     [M_*D_];
__device__ float g_h     [M_*DFF_];
__device__ float g_ff    [M_*D_];
__device__ float g_x2    [M_*D_];
__device__ float g_outp  [M_*OUTD_];

// ---------------- bilinear sampling of the (virtual) 224x224 upsample --------
// jax.image.resize(14->224, bilinear, half-pixel): src = (o+0.5)/16 - 0.5.
// Edge renormalization of the triangle kernel == clamped-index bilinear.
struct Bil { int i0,i1,j0,j1; float w00,w01,w10,w11; };

__device__ __forceinline__ Bil make_bil(int py, int px) {
    float cy = ((float)py + 0.5f) * (14.0f/224.0f) - 0.5f;
    float cx = ((float)px + 0.5f) * (14.0f/224.0f) - 0.5f;
    float fy = floorf(cy), fx = floorf(cx);
    float ay = cy - fy,    ax = cx - fx;
    int y0 = (int)fy, x0 = (int)fx;
    Bil b;
    b.i0 = min(13, max(0, y0));   b.i1 = min(13, max(0, y0+1));
    b.j0 = min(13, max(0, x0));   b.j1 = min(13, max(0, x0+1));
    b.w00 = (1.f-ay)*(1.f-ax); b.w01 = (1.f-ay)*ax;
    b.w10 = ay*(1.f-ax);       b.w11 = ay*ax;
    return b;
}

__device__ __forceinline__ float bil_sample(const float* __restrict__ f, int c, const Bil& b) {
    const float* p = f + c*196;
    return b.w00*p[b.i0*14 + b.j0] + b.w01*p[b.i0*14 + b.j1]
         + b.w10*p[b.i1*14 + b.j0] + b.w11*p[b.i1*14 + b.j1];
}

// ---------------- K0: roll-align first_boundary to previous_boundary ---------
__global__ void k_align(const int* __restrict__ prev, const int* __restrict__ first) {
    int b = blockIdx.x;
    __shared__ int sp[N_*2], sf[N_*2];
    __shared__ int sdist[N_];
    __shared__ int sbest;
    int t = threadIdx.x;
    for (int i = t; i < N_*2; i += blockDim.x) {
        sp[i] = prev [b*N_*2 + i];
        sf[i] = first[b*N_*2 + i];
    }
    __syncthreads();
    for (int s = t; s < N_; s += blockDim.x) {
        int acc = 0;
        for (int j = 0; j < N_; j++) {
            int jj = (j - s + N_) % N_;
            acc += abs(sp[j*2]   - sf[jj*2]);
            acc += abs(sp[j*2+1] - sf[jj*2+1]);
        }
        sdist[s] = acc;
    }
    __syncthreads();
    if (t == 0) {
        int bd = sdist[0], bs = 0;
        for (int s = 1; s < N_; s++) if (sdist[s] < bd) { bd = sdist[s]; bs = s; } // first-occurrence argmin
        sbest = bs;
    }
    __syncthreads();
    int best = sbest;
    for (int j = t; j < N_; j += blockDim.x) {
        int jj = (j - best + N_) % N_;
        g_firstal[(b*N_ + j)*2]     = sf[jj*2];
        g_firstal[(b*N_ + j)*2 + 1] = sf[jj*2+1];
    }
}

// ---------------- K1: gather pre_q / first_q, init curr ----------------------
__global__ void k_gather_pf(const float* __restrict__ pre_f,
                            const float* __restrict__ first_f,
                            const int* __restrict__ prev) {
    int row = blockIdx.x;          // b*N + n
    int b = row / N_;
    int py = prev[row*2], px = prev[row*2+1];
    Bil bp = make_bil(py, px);
    Bil bf = make_bil(g_firstal[row*2], g_firstal[row*2+1]);
    const float* pf = pre_f   + b*C_*196;
    const float* ff = first_f + b*C_*196;
    for (int c = threadIdx.x; c < C_; c += blockDim.x) {
        g_preq  [row*C_ + c] = bil_sample(pf, c, bp);
        g_firstq[row*C_ + c] = bil_sample(ff, c, bf);
    }
    if (threadIdx.x == 0) {
        g_curr[row*2]   = (float)py;
        g_curr[row*2+1] = (float)px;
    }
}

// ---------------- K2: positional encoding ------------------------------------
__global__ void k_pe() {
    int n = blockIdx.x;
    for (int d = threadIdx.x; d < D_; d += blockDim.x) {
        int k2 = d & ~1;   // even index 2k
        float div = expf((float)k2 * (-9.210340371976184f / (float)D_));
        float arg = (float)n * div;
        g_pe[n*D_ + d] = (d & 1) ? cosf(arg) : sinf(arg);
    }
}

// ---------------- K3: build tokens = LN(concat) + pe -------------------------
__global__ void k_tokens(const float* __restrict__ curr_f,
                         const float* __restrict__ lng,
                         const float* __restrict__ lnb) {
    int row = blockIdx.x;
    int b = row / N_, n = row % N_;
    __shared__ float srow[D_];
    __shared__ float red[256];
    int t = threadIdx.x;

    float cy = g_curr[row*2], cx = g_curr[row*2+1];
    int py = (int)cy, px = (int)cx;          // truncation (curr >= 0)
    Bil bb = make_bil(py, px);
    const float* cf = curr_f + b*C_*196;

    float lsum = 0.f;
    for (int d = t; d < D_; d += 256) {
        float v;
        if      (d < C_)        v = g_preq[row*C_ + d];
        else if (d < 2*C_)      v = bil_sample(cf, d - C_, bb);
        else if (d == 2*C_)     v = cy;
        else if (d == 2*C_+1)   v = cx;
        else                    v = g_firstq[row*C_ + (d - (2*C_+2))];
        srow[d] = v;
        lsum += v;
    }
    red[t] = lsum; __syncthreads();
    for (int s = 128; s >= 1; s >>= 1) { if (t < s) red[t] += red[t+s]; __syncthreads(); }
    float mean = red[0] * (1.f/(float)D_);
    __syncthreads();

    float lsq = 0.f;
    for (int d = t; d < D_; d += 256) { float u = srow[d] - mean; lsq += u*u; }
    red[t] = lsq; __syncthreads();
    for (int s = 128; s >= 1; s >>= 1) { if (t < s) red[t] += red[t+s]; __syncthreads(); }
    float rstd = rsqrtf(red[0] * (1.f/(float)D_) + 1e-5f);
    __syncthreads();

    for (int d = t; d < D_; d += 256)
        g_tokens[row*D_ + d] = lng[d] * ((srow[d] - mean) * rstd) + lnb[d] + g_pe[n*D_ + d];
}

// ---------------- generic GEMM: Out[M,N] = A[M,K] @ W[N,K]^T + bias ----------
#define BM 64
#define BN 128
#define BK 16
__global__ __launch_bounds__(256) void k_gemm(
    const float* __restrict__ A, const float* __restrict__ W,
    const float* __restrict__ bias, float* __restrict__ Out,
    int M, int Ncols, int K, int relu)
{
    __shared__ float As[BK][BM];
    __shared__ float Ws[BK][BN];
    int m0 = blockIdx.y * BM, n0 = blockIdx.x * BN;
    int t = threadIdx.x;
    int ty = t >> 4, tx = t & 15;
    float acc[4][8];
    #pragma unroll
    for (int i = 0; i < 4; i++)
        #pragma unroll
        for (int j = 0; j < 8; j++) acc[i][j] = 0.f;

    int ar = t >> 2, ac = (t & 3) * 4;   // A tile: 64 rows x 16 k, 4 elems/thread
    int wr = t >> 1, wc = (t & 1) * 8;   // W tile: 128 rows x 16 k, 8 elems/thread

    for (int k0 = 0; k0 < K; k0 += BK) {
        #pragma unroll
        for (int i = 0; i < 4; i++) {
            int k = k0 + ac + i, m = m0 + ar;
            As[ac+i][ar] = (m < M && k < K) ? A[m*K + k] : 0.f;
        }
        #pragma unroll
        for (int i = 0; i < 8; i++) {
            int k = k0 + wc + i, n = n0 + wr;
            Ws[wc+i][wr] = (n < Ncols && k < K) ? W[n*K + k] : 0.f;
        }
        __syncthreads();
        #pragma unroll
        for (int kk = 0; kk < BK; kk++) {
            float a[4], w[8];
            #pragma unroll
            for (int i = 0; i < 4; i++) a[i] = As[kk][ty*4 + i];
            #pragma unroll
            for (int j = 0; j < 8; j++) w[j] = Ws[kk][tx*8 + j];
            #pragma unroll
            for (int i = 0; i < 4; i++)
                #pragma unroll
                for (int j = 0; j < 8; j++)
                    acc[i][j] = fmaf(a[i], w[j], acc[i][j]);
        }
        __syncthreads();
    }
    #pragma unroll
    for (int i = 0; i < 4; i++) {
        int m = m0 + ty*4 + i;
        if (m >= M) continue;
        #pragma unroll
        for (int j = 0; j < 8; j++) {
            int n = n0 + tx*8 + j;
            if (n >= Ncols) continue;
            float v = acc[i][j] + bias[n];
            if (relu) v = fmaxf(v, 0.f);
            Out[m*Ncols + n] = v;
        }
    }
}

// ---------------- attention: per (b, q-row) block -----------------------------
__global__ void k_attn() {
    int row = blockIdx.x;                     // b*N + q
    int b = row / N_;
    __shared__ float qs[D_];
    __shared__ float sc[N_];
    const float* qp = g_qkv + row*TD_;
    for (int d = threadIdx.x; d < D_; d += blockDim.x) qs[d] = qp[d];
    __syncthreads();

    int warp = threadIdx.x >> 5, lane = threadIdx.x & 31;
    int nwarp = blockDim.x >> 5;
    float scale = rsqrtf((float)D_);
    for (int kn = warp; kn < N_; kn += nwarp) {
        const float* kp = g_qkv + (b*N_ + kn)*TD_ + D_;
        float acc = 0.f;
        for (int d = lane; d < D_; d += 32) acc += qs[d] * kp[d];
        #pragma unroll
        for (int o = 16; o > 0; o >>= 1) acc += __shfl_down_sync(0xffffffffu, acc, o);
        if (lane == 0) sc[kn] = acc * scale;
    }
    __syncthreads();
    if (threadIdx.x == 0) {
        float mx = sc[0];
        for (int i = 1; i < N_; i++) mx = fmaxf(mx, sc[i]);
        float s = 0.f;
        for (int i = 0; i < N_; i++) { float e = expf(sc[i] - mx); sc[i] = e; s += e; }
        float inv = 1.f / s;
        for (int i = 0; i < N_; i++) sc[i] *= inv;
    }
    __syncthreads();
    for (int d = threadIdx.x; d < D_; d += blockDim.x) {
        float acc = 0.f;
        const float* vp = g_qkv + b*N_*TD_ + 2*D_ + d;
        #pragma unroll 4
        for (int k = 0; k < N_; k++) acc += sc[k] * vp[k*TD_];
        g_av[row*D_ + d] = acc;
    }
}

// ---------------- layernorm with optional residual ---------------------------
__global__ void k_ln(const float* __restrict__ in0, const float* __restrict__ in1,
                     const float* __restrict__ g, const float* __restrict__ bta,
                     float* __restrict__ out) {
    int row = blockIdx.x;
    __shared__ float srow[D_];
    __shared__ float red[256];
    int t = threadIdx.x;
    float lsum = 0.f;
    for (int d = t; d < D_; d += 256) {
        float v = in0[row*D_ + d];
        if (in1) v += in1[row*D_ + d];
        srow[d] = v; lsum += v;
    }
    red[t] = lsum; __syncthreads();
    for (int s = 128; s >= 1; s >>= 1) { if (t < s) red[t] += red[t+s]; __syncthreads(); }
    float mean = red[0] * (1.f/(float)D_);
    __syncthreads();
    float lsq = 0.f;
    for (int d = t; d < D_; d += 256) { float u = srow[d] - mean; lsq += u*u; }
    red[t] = lsq; __syncthreads();
    for (int s = 128; s >= 1; s >>= 1) { if (t < s) red[t] += red[t+s]; __syncthreads(); }
    float rstd = rsqrtf(red[0] * (1.f/(float)D_) + 1e-5f);
    __syncthreads();
    for (int d = t; d < D_; d += 256)
        out[row*D_ + d] = g[d] * ((srow[d] - mean) * rstd) + bta[d];
}

// ---------------- update: pre_q += out[:C]; curr = clip(curr + out[C:]) ------
__global__ void k_update(float* __restrict__ dout, int iter) {
    int row = blockIdx.x;
    const float* o = g_outp + row*OUTD_;
    for (int c = threadIdx.x; c < C_; c += blockDim.x)
        g_preq[row*C_ + c] += o[c];
    if (threadIdx.x == 0) {
        float ny = fminf(fmaxf(g_curr[row*2]   + o[C_],   0.f), 223.f);
        float nx = fminf(fmaxf(g_curr[row*2+1] + o[C_+1], 0.f), 223.f);
        g_curr[row*2]   = ny;
        g_curr[row*2+1] = nx;
        dout[iter*(B_*N_*2) + row*2]     = ny;
        dout[iter*(B_*N_*2) + row*2 + 1] = nx;
    }
}

// ---------------- launch ------------------------------------------------------
extern "C" void kernel_launch(void* const* d_in, const int* in_sizes, int n_in,
                              void* d_out, int out_size) {
    (void)in_sizes; (void)n_in; (void)out_size;
    const float* pre_f   = (const float*)d_in[0];
    const float* curr_f  = (const float*)d_in[1];
    const float* first_f = (const float*)d_in[2];
    const int*   prev_b  = (const int*)  d_in[3];
    const int*   first_b = (const int*)  d_in[4];
    const float* lng = (const float*)d_in[5];
    const float* lnb = (const float*)d_in[6];
    const float* ipw = (const float*)d_in[7];
    const float* ipb = (const float*)d_in[8];
    const float* opw = (const float*)d_in[9];
    const float* opb = (const float*)d_in[10];
    const float* n1g = (const float*)d_in[11];
    const float* n1b = (const float*)d_in[12];
    const float* l1w = (const float*)d_in[13];
    const float* l1b = (const float*)d_in[14];
    const float* l2w = (const float*)d_in[15];
    const float* l2b = (const float*)d_in[16];
    const float* n2g = (const float*)d_in[17];
    const float* n2b = (const float*)d_in[18];
    const float* ow  = (const float*)d_in[19];
    const float* ob  = (const float*)d_in[20];

    float *p_tokens, *p_qkv, *p_av, *p_aproj, *p_x, *p_h, *p_ff, *p_x2, *p_outp;
    cudaGetSymbolAddress((void**)&p_tokens, g_tokens);
    cudaGetSymbolAddress((void**)&p_qkv,    g_qkv);
    cudaGetSymbolAddress((void**)&p_av,     g_av);
    cudaGetSymbolAddress((void**)&p_aproj,  g_aproj);
    cudaGetSymbolAddress((void**)&p_x,      g_x);
    cudaGetSymbolAddress((void**)&p_h,      g_h);
    cudaGetSymbolAddress((void**)&p_ff,     g_ff);
    cudaGetSymbolAddress((void**)&p_x2,     g_x2);
    cudaGetSymbolAddress((void**)&p_outp,   g_outp);

    k_align<<<B_, 128>>>(prev_b, first_b);
    k_gather_pf<<<M_, 256>>>(pre_f, first_f, prev_b);
    k_pe<<<N_, 256>>>();

    dim3 gq((TD_  + BN-1)/BN, (M_ + BM-1)/BM);  // qkv
    dim3 gd((D_   + BN-1)/BN, (M_ + BM-1)/BM);  // D-wide outputs
    dim3 gf((DFF_ + BN-1)/BN, (M_ + BM-1)/BM);  // ffn hidden
    dim3 go((OUTD_+ BN-1)/BN, (M_ + BM-1)/BM);  // final head

    for (int it = 0; it < REFINE_; it++) {
        k_tokens<<<M_, 256>>>(curr_f, lng, lnb);
        k_gemm<<<gq, 256>>>(p_tokens, ipw, ipb, p_qkv, M_, TD_, D_, 0);
        k_attn<<<M_, 128>>>();
        k_gemm<<<gd, 256>>>(p_av, opw, opb, p_aproj, M_, D_, D_, 0);
        k_ln<<<M_, 256>>>(p_tokens, p_aproj, n1g, n1b, p_x);
        k_gemm<<<gf, 256>>>(p_x, l1w, l1b, p_h, M_, DFF_, D_, 1);
        k_gemm<<<gd, 256>>>(p_h, l2w, l2b, p_ff, M_, D_, DFF_, 0);
        k_ln<<<M_, 256>>>(p_x, p_ff, n2g, n2b, p_x2);
        k_gemm<<<go, 256>>>(p_x2, ow, ob, p_outp, M_, OUTD_, D_, 0);
        k_update<<<M_, 256>>>((float*)d_out, it);
    }
}

// round 2
// speedup vs baseline: 2.3865x; 2.3865x over previous
#include <cuda_runtime.h>
#include <cuda_bf16.h>
#include <math.h>
#include <stdint.h>

#define B_    2
#define C_    1024
#define N_    80
#define D_    3074
#define KP    3104      // padded K (multiple of 32, 16B-aligned rows)
#define TD_   9222
#define DFF_  2048
#define OUTD_ 1026
#define M_    160
#define REFINE_ 3

// ---------------- bf16 weights (padded K stride) ------------------------------
__device__ __nv_bfloat16 g_ipw[(size_t)TD_*KP];
__device__ __nv_bfloat16 g_opw[(size_t)D_*KP];
__device__ __nv_bfloat16 g_l1w[(size_t)DFF_*KP];
__device__ __nv_bfloat16 g_l2w[(size_t)D_*DFF_];
__device__ __nv_bfloat16 g_oww[(size_t)OUTD_*KP];

// ---------------- fp32 activations --------------------------------------------
__device__ float g_preq  [M_*C_];
__device__ float g_firstq[M_*C_];
__device__ float g_pe    [N_*D_];
__device__ float g_curr  [M_*2];
__device__ int   g_firstal[M_*2];
__device__ float g_tokens[M_*KP];
__device__ float g_q     [M_*KP];
__device__ float g_k     [M_*KP];
__device__ float g_v     [M_*KP];
__device__ float g_av    [M_*KP];
__device__ float g_aproj [M_*KP];
__device__ float g_x     [M_*KP];
__device__ float g_h     [M_*DFF_];
__device__ float g_ff    [M_*KP];
__device__ float g_x2    [M_*KP];
__device__ float g_outp  [M_*OUTD_];

// ---------------- bilinear sampling (virtual 224x224 upsample) ----------------
struct Bil { int i0,i1,j0,j1; float w00,w01,w10,w11; };

__device__ __forceinline__ Bil make_bil(int py, int px) {
    float cy = ((float)py + 0.5f) * (14.0f/224.0f) - 0.5f;
    float cx = ((float)px + 0.5f) * (14.0f/224.0f) - 0.5f;
    float fy = floorf(cy), fx = floorf(cx);
    float ay = cy - fy,    ax = cx - fx;
    int y0 = (int)fy, x0 = (int)fx;
    Bil b;
    b.i0 = min(13, max(0, y0));   b.i1 = min(13, max(0, y0+1));
    b.j0 = min(13, max(0, x0));   b.j1 = min(13, max(0, x0+1));
    b.w00 = (1.f-ay)*(1.f-ax); b.w01 = (1.f-ay)*ax;
    b.w10 = ay*(1.f-ax);       b.w11 = ay*ax;
    return b;
}

__device__ __forceinline__ float bil_sample(const float* __restrict__ f, int c, const Bil& b) {
    const float* p = f + c*196;
    return b.w00*p[b.i0*14 + b.j0] + b.w01*p[b.i0*14 + b.j1]
         + b.w10*p[b.i1*14 + b.j0] + b.w11*p[b.i1*14 + b.j1];
}

// ---------------- K0: roll-align first_boundary --------------------------------
__global__ void k_align(const int* __restrict__ prev, const int* __restrict__ first) {
    int b = blockIdx.x;
    __shared__ int sp[N_*2], sf[N_*2];
    __shared__ int sdist[N_];
    __shared__ int sbest;
    int t = threadIdx.x;
    for (int i = t; i < N_*2; i += blockDim.x) {
        sp[i] = prev [b*N_*2 + i];
        sf[i] = first[b*N_*2 + i];
    }
    __syncthreads();
    for (int s = t; s < N_; s += blockDim.x) {
        int acc = 0;
        for (int j = 0; j < N_; j++) {
            int jj = (j - s + N_) % N_;
            acc += abs(sp[j*2]   - sf[jj*2]);
            acc += abs(sp[j*2+1] - sf[jj*2+1]);
        }
        sdist[s] = acc;
    }
    __syncthreads();
    if (t == 0) {
        int bd = sdist[0], bs = 0;
        for (int s = 1; s < N_; s++) if (sdist[s] < bd) { bd = sdist[s]; bs = s; }
        sbest = bs;
    }
    __syncthreads();
    int best = sbest;
    for (int j = t; j < N_; j += blockDim.x) {
        int jj = (j - best + N_) % N_;
        g_firstal[(b*N_ + j)*2]     = sf[jj*2];
        g_firstal[(b*N_ + j)*2 + 1] = sf[jj*2+1];
    }
}

// ---------------- K1: gather pre_q / first_q, init curr ------------------------
__global__ void k_gather_pf(const float* __restrict__ pre_f,
                            const float* __restrict__ first_f,
                            const int* __restrict__ prev) {
    int row = blockIdx.x;
    int b = row / N_;
    int py = prev[row*2], px = prev[row*2+1];
    Bil bp = make_bil(py, px);
    Bil bf = make_bil(g_firstal[row*2], g_firstal[row*2+1]);
    const float* pf = pre_f   + b*C_*196;
    const float* ff = first_f + b*C_*196;
    for (int c = threadIdx.x; c < C_; c += blockDim.x) {
        g_preq  [row*C_ + c] = bil_sample(pf, c, bp);
        g_firstq[row*C_ + c] = bil_sample(ff, c, bf);
    }
    if (threadIdx.x == 0) {
        g_curr[row*2]   = (float)py;
        g_curr[row*2+1] = (float)px;
    }
}

// ---------------- K2: positional encoding --------------------------------------
__global__ void k_pe() {
    int n = blockIdx.x;
    for (int d = threadIdx.x; d < D_; d += blockDim.x) {
        int k2 = d & ~1;
        float div = expf((float)k2 * (-9.210340371976184f / (float)D_));
        float arg = (float)n * div;
        g_pe[n*D_ + d] = (d & 1) ? cosf(arg) : sinf(arg);
    }
}

// ---------------- weight conversion fp32 -> bf16 (K-padded) --------------------
__global__ void k_w2bf(const float* __restrict__ src, __nv_bfloat16* __restrict__ dst,
                       int K, int Kp) {
    int row = blockIdx.x;
    const float* s = src + (size_t)row*K;
    __nv_bfloat16* d = dst + (size_t)row*Kp;
    for (int k = threadIdx.x; k < Kp; k += blockDim.x)
        d[k] = (k < K) ? __float2bfloat16(s[k]) : __float2bfloat16(0.f);
}

// ---------------- zero q/k/v pad columns (once per launch) ---------------------
__global__ void k_zero_qkvpad() {
    int r = blockIdx.x, t = threadIdx.x;
    if (t < KP - D_) {
        g_q[(size_t)r*KP + D_ + t] = 0.f;
        g_k[(size_t)r*KP + D_ + t] = 0.f;
        g_v[(size_t)r*KP + D_ + t] = 0.f;
    }
}

// ---------------- K3: tokens = LN(concat) + pe  (stride KP, pad zeroed) --------
__global__ void k_tokens(const float* __restrict__ curr_f,
                         const float* __restrict__ lng,
                         const float* __restrict__ lnb) {
    int row = blockIdx.x;
    int b = row / N_, n = row % N_;
    __shared__ float srow[D_];
    __shared__ float red[256];
    int t = threadIdx.x;

    float cy = g_curr[row*2], cx = g_curr[row*2+1];
    int py = (int)cy, px = (int)cx;
    Bil bb = make_bil(py, px);
    const float* cf = curr_f + b*C_*196;

    float lsum = 0.f;
    for (int d = t; d < D_; d += 256) {
        float v;
        if      (d < C_)        v = g_preq[row*C_ + d];
        else if (d < 2*C_)      v = bil_sample(cf, d - C_, bb);
        else if (d == 2*C_)     v = cy;
        else if (d == 2*C_+1)   v = cx;
        else                    v = g_firstq[row*C_ + (d - (2*C_+2))];
        srow[d] = v;
        lsum += v;
    }
    red[t] = lsum; __syncthreads();
    for (int s = 128; s >= 1; s >>= 1) { if (t < s) red[t] += red[t+s]; __syncthreads(); }
    float mean = red[0] * (1.f/(float)D_);
    __syncthreads();

    float lsq = 0.f;
    for (int d = t; d < D_; d += 256) { float u = srow[d] - mean; lsq += u*u; }
    red[t] = lsq; __syncthreads();
    for (int s = 128; s >= 1; s >>= 1) { if (t < s) red[t] += red[t+s]; __syncthreads(); }
    float rstd = rsqrtf(red[0] * (1.f/(float)D_) + 1e-5f);
    __syncthreads();

    for (int d = t; d < KP; d += 256) {
        float v = (d < D_) ? (lng[d] * ((srow[d] - mean) * rstd) + lnb[d] + g_pe[n*D_ + d]) : 0.f;
        g_tokens[(size_t)row*KP + d] = v;
    }
}

// ---------------- bf16 tensor-core GEMM ----------------------------------------
// Out[M,N] = A[M,Kp](fp32) @ W[N,Kp](bf16)^T + bias.
// mode 0: plain, 1: relu, 2: qkv split-store into g_q/g_k/g_v (stride KP).
__device__ __forceinline__ void mma16816(float c[4], const uint32_t a[4], const uint32_t b[2]) {
    asm volatile(
        "mma.sync.aligned.m16n8k16.row.col.f32.bf16.bf16.f32 "
        "{%0,%1,%2,%3},{%4,%5,%6,%7},{%8,%9},{%0,%1,%2,%3};"
        : "+f"(c[0]), "+f"(c[1]), "+f"(c[2]), "+f"(c[3])
        : "r"(a[0]), "r"(a[1]), "r"(a[2]), "r"(a[3]), "r"(b[0]), "r"(b[1]));
}

#define GBM 64
#define GBN 128
#define GBK 32

__global__ __launch_bounds__(256) void k_gemm_mma(
    const float* __restrict__ A, int lda,
    const __nv_bfloat16* __restrict__ W, int ldw,
    const float* __restrict__ bias,
    float* __restrict__ Out, int ldo,
    int M, int N, int Kp, int mode,
    float* __restrict__ oq, float* __restrict__ ok, float* __restrict__ ov)
{
    __shared__ __nv_bfloat16 As[GBM][GBK + 8];   // 40 bf16 row stride (80B)
    __shared__ __nv_bfloat16 Ws[GBN][GBK + 8];

    int m0 = blockIdx.y * GBM, n0 = blockIdx.x * GBN;
    int t = threadIdx.x, lane = t & 31, warp = t >> 5;
    int wm = (warp >> 2) * 32;        // 2 warps along M
    int wn = (warp & 3) * 32;         // 4 warps along N

    float acc[2][4][4];
    #pragma unroll
    for (int i = 0; i < 2; i++)
        #pragma unroll
        for (int j = 0; j < 4; j++)
            #pragma unroll
            for (int r = 0; r < 4; r++) acc[i][j][r] = 0.f;

    int a_row = t >> 2, a_col = (t & 3) * 8;   // 64 rows x (4 thr * 8 elems)
    int w_row = t >> 1, w_col = (t & 1) * 16;  // 128 rows x (2 thr * 16 elems)
    int qr = lane >> 2, qc2 = (lane & 3) * 2;

    for (int k0 = 0; k0 < Kp; k0 += GBK) {
        // ---- A tile (fp32 -> bf16) ----
        {
            uint4 pk = make_uint4(0u, 0u, 0u, 0u);
            int m = m0 + a_row;
            if (m < M) {
                const float4* p = (const float4*)(A + (size_t)m*lda + k0 + a_col);
                float4 f0 = p[0], f1 = p[1];
                __nv_bfloat162 b0 = __float22bfloat162_rn(make_float2(f0.x, f0.y));
                __nv_bfloat162 b1 = __float22bfloat162_rn(make_float2(f0.z, f0.w));
                __nv_bfloat162 b2 = __float22bfloat162_rn(make_float2(f1.x, f1.y));
                __nv_bfloat162 b3 = __float22bfloat162_rn(make_float2(f1.z, f1.w));
                pk.x = *(uint32_t*)&b0; pk.y = *(uint32_t*)&b1;
                pk.z = *(uint32_t*)&b2; pk.w = *(uint32_t*)&b3;
            }
            *(uint4*)&As[a_row][a_col] = pk;
        }
        // ---- W tile ----
        {
            uint4 w0 = make_uint4(0u,0u,0u,0u), w1 = make_uint4(0u,0u,0u,0u);
            int n = n0 + w_row;
            if (n < N) {
                const uint4* p = (const uint4*)(W + (size_t)n*ldw + k0 + w_col);
                w0 = p[0]; w1 = p[1];
            }
            *(uint4*)&Ws[w_row][w_col]     = w0;
            *(uint4*)&Ws[w_row][w_col + 8] = w1;
        }
        __syncthreads();

        #pragma unroll
        for (int kk = 0; kk < GBK; kk += 16) {
            uint32_t af[2][4], bfm[4][2];
            #pragma unroll
            for (int i = 0; i < 2; i++) {
                int r = wm + i*16 + qr;
                af[i][0] = *(const uint32_t*)&As[r    ][kk + qc2];
                af[i][1] = *(const uint32_t*)&As[r + 8][kk + qc2];
                af[i][2] = *(const uint32_t*)&As[r    ][kk + qc2 + 8];
                af[i][3] = *(const uint32_t*)&As[r + 8][kk + qc2 + 8];
            }
            #pragma unroll
            for (int j = 0; j < 4; j++) {
                int rn = wn + j*8 + qr;
                bfm[j][0] = *(const uint32_t*)&Ws[rn][kk + qc2];
                bfm[j][1] = *(const uint32_t*)&Ws[rn][kk + qc2 + 8];
            }
            #pragma unroll
            for (int i = 0; i < 2; i++)
                #pragma unroll
                for (int j = 0; j < 4; j++)
                    mma16816(acc[i][j], af[i], bfm[j]);
        }
        __syncthreads();
    }

    // ---- epilogue ----
    #pragma unroll
    for (int i = 0; i < 2; i++) {
        #pragma unroll
        for (int j = 0; j < 4; j++) {
            int nb = n0 + wn + j*8 + qc2;
            #pragma unroll
            for (int h = 0; h < 2; h++) {           // row halves (m, m+8)
                int m = m0 + wm + i*16 + qr + h*8;
                if (m >= M) continue;
                #pragma unroll
                for (int c = 0; c < 2; c++) {       // col pair
                    int n = nb + c;
                    if (n >= N) continue;
                    float v = acc[i][j][h*2 + c] + bias[n];
                    if (mode == 1) v = fmaxf(v, 0.f);
                    if (mode == 2) {
                        int seg = (n >= 6148) ? 2 : (n >= 3074 ? 1 : 0);
                        int col = n - seg*3074;
                        float* dst = (seg == 0) ? oq : (seg == 1 ? ok : ov);
                        dst[(size_t)m*KP + col] = v;
                    } else {
                        Out[(size_t)m*ldo + n] = v;
                    }
                }
            }
        }
    }
}

// ---------------- attention: 16 q-rows per block, float4, padded ---------------
__global__ __launch_bounds__(512) void k_attn2() {
    int q0 = blockIdx.x * 16;
    int b = q0 / N_;                      // 16 | 80, block never straddles b
    int w = threadIdx.x >> 5, lane = threadIdx.x & 31;
    int r = q0 + w;
    __shared__ float ssc[16][N_];

    const float4* qp = (const float4*)&g_q[(size_t)r*KP];
    float scale = rsqrtf((float)D_);

    for (int kn = 0; kn < N_; kn++) {
        const float4* kp = (const float4*)&g_k[(size_t)(b*N_ + kn)*KP];
        float acc = 0.f;
        for (int d4 = lane; d4 < KP/4; d4 += 32) {
            float4 qv = qp[d4], kv = kp[d4];
            acc += qv.x*kv.x + qv.y*kv.y + qv.z*kv.z + qv.w*kv.w;
        }
        #pragma unroll
        for (int o = 16; o > 0; o >>= 1) acc += __shfl_down_sync(0xffffffffu, acc, o);
        if (lane == 0) ssc[w][kn] = acc * scale;
    }
    __syncwarp();

    // softmax over 80 (per warp)
    float mx = -1e30f;
    for (int i = lane; i < N_; i += 32) mx = fmaxf(mx, ssc[w][i]);
    #pragma unroll
    for (int o = 16; o > 0; o >>= 1) mx = fmaxf(mx, __shfl_xor_sync(0xffffffffu, mx, o));
    float s = 0.f;
    for (int i = lane; i < N_; i += 32) { float e = expf(ssc[w][i] - mx); ssc[w][i] = e; s += e; }
    #pragma unroll
    for (int o = 16; o > 0; o >>= 1) s += __shfl_xor_sync(0xffffffffu, s, o);
    float inv = 1.f / s;
    __syncwarp();
    for (int i = lane; i < N_; i += 32) ssc[w][i] *= inv;
    __syncwarp();

    // AV (covers pad -> av pad = 0 since v pad = 0)
    float4* op = (float4*)&g_av[(size_t)r*KP];
    const float4* vb = (const float4*)&g_v[(size_t)b*N_*KP];
    for (int d4 = lane; d4 < KP/4; d4 += 32) {
        float4 acc = make_float4(0.f, 0.f, 0.f, 0.f);
        #pragma unroll 4
        for (int k = 0; k < N_; k++) {
            float4 vv = vb[(size_t)k*(KP/4) + d4];
            float sck = ssc[w][k];
            acc.x += sck*vv.x; acc.y += sck*vv.y; acc.z += sck*vv.z; acc.w += sck*vv.w;
        }
        op[d4] = acc;
    }
}

// ---------------- layernorm with residual (stride KP, pad zeroed) --------------
__global__ void k_ln(const float* __restrict__ in0, const float* __restrict__ in1,
                     const float* __restrict__ g, const float* __restrict__ bta,
                     float* __restrict__ out) {
    int row = blockIdx.x;
    __shared__ float srow[D_];
    __shared__ float red[256];
    int t = threadIdx.x;
    float lsum = 0.f;
    for (int d = t; d < D_; d += 256) {
        float v = in0[(size_t)row*KP + d];
        if (in1) v += in1[(size_t)row*KP + d];
        srow[d] = v; lsum += v;
    }
    red[t] = lsum; __syncthreads();
    for (int s = 128; s >= 1; s >>= 1) { if (t < s) red[t] += red[t+s]; __syncthreads(); }
    float mean = red[0] * (1.f/(float)D_);
    __syncthreads();
    float lsq = 0.f;
    for (int d = t; d < D_; d += 256) { float u = srow[d] - mean; lsq += u*u; }
    red[t] = lsq; __syncthreads();
    for (int s = 128; s >= 1; s >>= 1) { if (t < s) red[t] += red[t+s]; __syncthreads(); }
    float rstd = rsqrtf(red[0] * (1.f/(float)D_) + 1e-5f);
    __syncthreads();
    for (int d = t; d < KP; d += 256) {
        float v = (d < D_) ? (g[d] * ((srow[d] - mean) * rstd) + bta[d]) : 0.f;
        out[(size_t)row*KP + d] = v;
    }
}

// ---------------- update -------------------------------------------------------
__global__ void k_update(float* __restrict__ dout, int iter) {
    int row = blockIdx.x;
    const float* o = g_outp + (size_t)row*OUTD_;
    for (int c = threadIdx.x; c < C_; c += blockDim.x)
        g_preq[row*C_ + c] += o[c];
    if (threadIdx.x == 0) {
        float ny = fminf(fmaxf(g_curr[row*2]   + o[C_],   0.f), 223.f);
        float nx = fminf(fmaxf(g_curr[row*2+1] + o[C_+1], 0.f), 223.f);
        g_curr[row*2]   = ny;
        g_curr[row*2+1] = nx;
        dout[iter*(B_*N_*2) + row*2]     = ny;
        dout[iter*(B_*N_*2) + row*2 + 1] = nx;
    }
}

// ---------------- launch --------------------------------------------------------
extern "C" void kernel_launch(void* const* d_in, const int* in_sizes, int n_in,
                              void* d_out, int out_size) {
    (void)in_sizes; (void)n_in; (void)out_size;
    const float* pre_f   = (const float*)d_in[0];
    const float* curr_f  = (const float*)d_in[1];
    const float* first_f = (const float*)d_in[2];
    const int*   prev_b  = (const int*)  d_in[3];
    const int*   first_b = (const int*)  d_in[4];
    const float* lng = (const float*)d_in[5];
    const float* lnb = (const float*)d_in[6];
    const float* ipw = (const float*)d_in[7];
    const float* ipb = (const float*)d_in[8];
    const float* opw = (const float*)d_in[9];
    const float* opb = (const float*)d_in[10];
    const float* n1g = (const float*)d_in[11];
    const float* n1b = (const float*)d_in[12];
    const float* l1w = (const float*)d_in[13];
    const float* l1b = (const float*)d_in[14];
    const float* l2w = (const float*)d_in[15];
    const float* l2b = (const float*)d_in[16];
    const float* n2g = (const float*)d_in[17];
    const float* n2b = (const float*)d_in[18];
    const float* ow  = (const float*)d_in[19];
    const float* ob  = (const float*)d_in[20];

    __nv_bfloat16 *p_ipw, *p_opw, *p_l1w, *p_l2w, *p_oww;
    cudaGetSymbolAddress((void**)&p_ipw, g_ipw);
    cudaGetSymbolAddress((void**)&p_opw, g_opw);
    cudaGetSymbolAddress((void**)&p_l1w, g_l1w);
    cudaGetSymbolAddress((void**)&p_l2w, g_l2w);
    cudaGetSymbolAddress((void**)&p_oww, g_oww);

    float *p_tokens, *p_q, *p_k, *p_v, *p_av, *p_aproj, *p_x, *p_h, *p_ff, *p_x2, *p_outp;
    cudaGetSymbolAddress((void**)&p_tokens, g_tokens);
    cudaGetSymbolAddress((void**)&p_q,      g_q);
    cudaGetSymbolAddress((void**)&p_k,      g_k);
    cudaGetSymbolAddress((void**)&p_v,      g_v);
    cudaGetSymbolAddress((void**)&p_av,     g_av);
    cudaGetSymbolAddress((void**)&p_aproj,  g_aproj);
    cudaGetSymbolAddress((void**)&p_x,      g_x);
    cudaGetSymbolAddress((void**)&p_h,      g_h);
    cudaGetSymbolAddress((void**)&p_ff,     g_ff);
    cudaGetSymbolAddress((void**)&p_x2,     g_x2);
    cudaGetSymbolAddress((void**)&p_outp,   g_outp);

    // prologue
    k_align<<<B_, 128>>>(prev_b, first_b);
    k_gather_pf<<<M_, 256>>>(pre_f, first_f, prev_b);
    k_pe<<<N_, 256>>>();
    k_zero_qkvpad<<<M_, 32>>>();

    // weight conversion (bf16, K-padded)
    k_w2bf<<<TD_,  256>>>(ipw, p_ipw, D_,   KP);
    k_w2bf<<<D_,   256>>>(opw, p_opw, D_,   KP);
    k_w2bf<<<DFF_, 256>>>(l1w, p_l1w, D_,   KP);
    k_w2bf<<<D_,   256>>>(l2w, p_l2w, DFF_, DFF_);
    k_w2bf<<<OUTD_,256>>>(ow,  p_oww, D_,   KP);

    dim3 gqkv((TD_  + GBN-1)/GBN, (M_ + GBM-1)/GBM);
    dim3 gop ((D_   + GBN-1)/GBN, (M_ + GBM-1)/GBM);
    dim3 gl1 ((DFF_ + GBN-1)/GBN, (M_ + GBM-1)/GBM);
    dim3 gout((OUTD_+ GBN-1)/GBN, (M_ + GBM-1)/GBM);

    for (int it = 0; it < REFINE_; it++) {
        k_tokens<<<M_, 256>>>(curr_f, lng, lnb);
        k_gemm_mma<<<gqkv, 256>>>(p_tokens, KP, p_ipw, KP, ipb,
                                  nullptr, 0, M_, TD_, KP, 2, p_q, p_k, p_v);
        k_attn2<<<M_/16, 512>>>();
        k_gemm_mma<<<gop, 256>>>(p_av, KP, p_opw, KP, opb,
                                 p_aproj, KP, M_, D_, KP, 0, nullptr, nullptr, nullptr);
        k_ln<<<M_, 256>>>(p_tokens, p_aproj, n1g, n1b, p_x);
        k_gemm_mma<<<gl1, 256>>>(p_x, KP, p_l1w, KP, l1b,
                                 p_h, DFF_, M_, DFF_, KP, 1, nullptr, nullptr, nullptr);
        k_gemm_mma<<<gop, 256>>>(p_h, DFF_, p_l2w, DFF_, l2b,
                                 p_ff, KP, M_, D_, DFF_, 0, nullptr, nullptr, nullptr);
        k_ln<<<M_, 256>>>(p_x, p_ff, n2g, n2b, p_x2);
        k_gemm_mma<<<gout, 256>>>(p_x2, KP, p_oww, KP, ob,
                                  p_outp, OUTD_, M_, OUTD_, KP, 0, nullptr, nullptr, nullptr);
        k_update<<<M_, 256>>>((float*)d_out, it);
    }
}

// round 7
// speedup vs baseline: 2.4631x; 1.0321x over previous
#include <cuda_runtime.h>
#include <cuda_bf16.h>
#include <math.h>
#include <stdint.h>

#define B_    2
#define C_    1024
#define N_    80
#define D_    3074
#define KP    3136      // padded K (multiple of 32)
#define TD_   9222
#define DFF_  2048
#define OUTD_ 1026
#define M_    160
#define REFINE_ 3

// ---------------- bf16 weights (padded K stride) ------------------------------
__device__ __nv_bfloat16 g_ipw[(size_t)TD_*KP];
__device__ __nv_bfloat16 g_opw[(size_t)D_*KP];
__device__ __nv_bfloat16 g_l1w[(size_t)DFF_*KP];
__device__ __nv_bfloat16 g_l2w[(size_t)D_*DFF_];
__device__ __nv_bfloat16 g_oww[(size_t)OUTD_*KP];

// ---------------- activations ---------------------------------------------------
__device__ float g_preq  [M_*C_];
__device__ float g_firstq[M_*C_];
__device__ float g_pe    [N_*D_];
__device__ float g_curr  [M_*2];
__device__ int   g_firstal[M_*2];
__device__ float g_tokens[M_*KP];
__device__ float g_q     [M_*KP];
__device__ float g_k     [M_*KP];
__device__ float g_v     [M_*KP];
__device__ float g_aproj [M_*KP];
__device__ float g_x     [M_*KP];
__device__ float g_ff    [M_*KP];
__device__ float g_x2    [M_*KP];
__device__ float g_outp  [M_*OUTD_];
// bf16 GEMM A-inputs
__device__ __nv_bfloat16 g_tok_bf[M_*KP];
__device__ __nv_bfloat16 g_av_bf [M_*KP];
__device__ __nv_bfloat16 g_x_bf  [M_*KP];
__device__ __nv_bfloat16 g_h_bf  [M_*DFF_];
__device__ __nv_bfloat16 g_x2_bf [M_*KP];

// ================= helpers =======================================================
__device__ __forceinline__ uint32_t smem_u32(const void* p) {
    uint32_t a;
    asm("{ .reg .u64 t; cvta.to.shared.u64 t, %1; cvt.u32.u64 %0, t; }" : "=r"(a) : "l"(p));
    return a;
}

__device__ __forceinline__ void cp_async16(uint32_t dst, const void* src, uint32_t srcsize) {
    asm volatile("cp.async.cg.shared.global [%0], [%1], 16, %2;"
                 :: "r"(dst), "l"(src), "r"(srcsize) : "memory");
}
__device__ __forceinline__ void cp_commit() {
    asm volatile("cp.async.commit_group;" ::: "memory");
}
__device__ __forceinline__ void cp_wait1() {
    asm volatile("cp.async.wait_group 1;" ::: "memory");
}

__device__ __forceinline__ void mma16816(float c[4], const uint32_t a[4], const uint32_t b[2]) {
    asm volatile(
        "mma.sync.aligned.m16n8k16.row.col.f32.bf16.bf16.f32 "
        "{%0,%1,%2,%3},{%4,%5,%6,%7},{%8,%9},{%0,%1,%2,%3};"
        : "+f"(c[0]), "+f"(c[1]), "+f"(c[2]), "+f"(c[3])
        : "r"(a[0]), "r"(a[1]), "r"(a[2]), "r"(a[3]), "r"(b[0]), "r"(b[1]));
}

// ================= bilinear sampling ============================================
struct Bil { int i0,i1,j0,j1; float w00,w01,w10,w11; };

__device__ __forceinline__ Bil make_bil(int py, int px) {
    float cy = ((float)py + 0.5f) * (14.0f/224.0f) - 0.5f;
    float cx = ((float)px + 0.5f) * (14.0f/224.0f) - 0.5f;
    float fy = floorf(cy), fx = floorf(cx);
    float ay = cy - fy,    ax = cx - fx;
    int y0 = (int)fy, x0 = (int)fx;
    Bil b;
    b.i0 = min(13, max(0, y0));   b.i1 = min(13, max(0, y0+1));
    b.j0 = min(13, max(0, x0));   b.j1 = min(13, max(0, x0+1));
    b.w00 = (1.f-ay)*(1.f-ax); b.w01 = (1.f-ay)*ax;
    b.w10 = ay*(1.f-ax);       b.w11 = ay*ax;
    return b;
}

__device__ __forceinline__ float bil_sample(const float* __restrict__ f, int c, const Bil& b) {
    const float* p = f + c*196;
    return b.w00*p[b.i0*14 + b.j0] + b.w01*p[b.i0*14 + b.j1]
         + b.w10*p[b.i1*14 + b.j0] + b.w11*p[b.i1*14 + b.j1];
}

// ================= prologue kernels =============================================
__global__ void k_align(const int* __restrict__ prev, const int* __restrict__ first) {
    int b = blockIdx.x;
    __shared__ int sp[N_*2], sf[N_*2];
    __shared__ int sdist[N_];
    __shared__ int sbest;
    int t = threadIdx.x;
    for (int i = t; i < N_*2; i += blockDim.x) {
        sp[i] = prev [b*N_*2 + i];
        sf[i] = first[b*N_*2 + i];
    }
    __syncthreads();
    for (int s = t; s < N_; s += blockDim.x) {
        int acc = 0;
        for (int j = 0; j < N_; j++) {
            int jj = (j - s + N_) % N_;
            acc += abs(sp[j*2]   - sf[jj*2]);
            acc += abs(sp[j*2+1] - sf[jj*2+1]);
        }
        sdist[s] = acc;
    }
    __syncthreads();
    if (t == 0) {
        int bd = sdist[0], bs = 0;
        for (int s = 1; s < N_; s++) if (sdist[s] < bd) { bd = sdist[s]; bs = s; }
        sbest = bs;
    }
    __syncthreads();
    int best = sbest;
    for (int j = t; j < N_; j += blockDim.x) {
        int jj = (j - best + N_) % N_;
        g_firstal[(b*N_ + j)*2]     = sf[jj*2];
        g_firstal[(b*N_ + j)*2 + 1] = sf[jj*2+1];
    }
}

__global__ void k_gather_pf(const float* __restrict__ pre_f,
                            const float* __restrict__ first_f,
                            const int* __restrict__ prev) {
    int row = blockIdx.x;
    int b = row / N_;
    int py = prev[row*2], px = prev[row*2+1];
    Bil bp = make_bil(py, px);
    Bil bf = make_bil(g_firstal[row*2], g_firstal[row*2+1]);
    const float* pf = pre_f   + b*C_*196;
    const float* ff = first_f + b*C_*196;
    for (int c = threadIdx.x; c < C_; c += blockDim.x) {
        g_preq  [row*C_ + c] = bil_sample(pf, c, bp);
        g_firstq[row*C_ + c] = bil_sample(ff, c, bf);
    }
    if (threadIdx.x == 0) {
        g_curr[row*2]   = (float)py;
        g_curr[row*2+1] = (float)px;
    }
}

__global__ void k_pe() {
    int n = blockIdx.x;
    for (int d = threadIdx.x; d < D_; d += blockDim.x) {
        int k2 = d & ~1;
        float div = expf((float)k2 * (-9.210340371976184f / (float)D_));
        float arg = (float)n * div;
        g_pe[n*D_ + d] = (d & 1) ? cosf(arg) : sinf(arg);
    }
}

__global__ void k_w2bf(const float* __restrict__ src, __nv_bfloat16* __restrict__ dst,
                       int K, int Kp) {
    int row = blockIdx.x;
    const float* s = src + (size_t)row*K;
    __nv_bfloat16* d = dst + (size_t)row*Kp;
    for (int k = threadIdx.x; k < Kp; k += blockDim.x)
        d[k] = (k < K) ? __float2bfloat16(s[k]) : __float2bfloat16(0.f);
}

__global__ void k_zero_qkvpad() {
    int r = blockIdx.x, t = threadIdx.x;
    if (t < KP - D_) {
        g_q[(size_t)r*KP + D_ + t] = 0.f;
        g_k[(size_t)r*KP + D_ + t] = 0.f;
        g_v[(size_t)r*KP + D_ + t] = 0.f;
    }
}

// ================= tokens = LN(concat) + pe  (fp32 + bf16) ======================
__global__ void k_tokens(const float* __restrict__ curr_f,
                         const float* __restrict__ lng,
                         const float* __restrict__ lnb) {
    int row = blockIdx.x;
    int b = row / N_, n = row % N_;
    __shared__ float srow[D_];
    __shared__ float red[256];
    int t = threadIdx.x;

    float cy = g_curr[row*2], cx = g_curr[row*2+1];
    int py = (int)cy, px = (int)cx;
    Bil bb = make_bil(py, px);
    const float* cf = curr_f + b*C_*196;

    float lsum = 0.f;
    for (int d = t; d < D_; d += 256) {
        float v;
        if      (d < C_)        v = g_preq[row*C_ + d];
        else if (d < 2*C_)      v = bil_sample(cf, d - C_, bb);
        else if (d == 2*C_)     v = cy;
        else if (d == 2*C_+1)   v = cx;
        else                    v = g_firstq[row*C_ + (d - (2*C_+2))];
        srow[d] = v;
        lsum += v;
    }
    red[t] = lsum; __syncthreads();
    for (int s = 128; s >= 1; s >>= 1) { if (t < s) red[t] += red[t+s]; __syncthreads(); }
    float mean = red[0] * (1.f/(float)D_);
    __syncthreads();

    float lsq = 0.f;
    for (int d = t; d < D_; d += 256) { float u = srow[d] - mean; lsq += u*u; }
    red[t] = lsq; __syncthreads();
    for (int s = 128; s >= 1; s >>= 1) { if (t < s) red[t] += red[t+s]; __syncthreads(); }
    float rstd = rsqrtf(red[0] * (1.f/(float)D_) + 1e-5f);
    __syncthreads();

    for (int d = t; d < KP; d += 256) {
        float v = (d < D_) ? (lng[d] * ((srow[d] - mean) * rstd) + lnb[d] + g_pe[n*D_ + d]) : 0.f;
        g_tokens[(size_t)row*KP + d] = v;
        g_tok_bf[(size_t)row*KP + d] = __float2bfloat16(v);
    }
}

// ================= GEMM: mma.sync + cp.async 3-stage pipeline ===================
// Out[160,N] = A[160,K](bf16) @ W[N,K](bf16)^T + bias
// Block tile 160x64xK; 8 warps (2x4); warp tile 80x16.
// modes: 0 -> fp32 OutF; 1 -> relu, bf16 OutB; 2 -> qkv split fp32 q/k/v
#define GSTAGES 3
#define A_STAGE_B 12800            // 160 rows * 80 B
#define W_STAGE_B 5120             // 64 rows * 80 B
#define W_REGION_OFF (GSTAGES * A_STAGE_B)              // 38400
#define GEMM_SMEM (GSTAGES * (A_STAGE_B + W_STAGE_B))   // 53760

__global__ __launch_bounds__(256) void k_gemm(
    const __nv_bfloat16* __restrict__ A, int lda,
    const __nv_bfloat16* __restrict__ W, int ldw,
    const float* __restrict__ bias,
    float* __restrict__ OutF, int ldo,
    __nv_bfloat16* __restrict__ OutB, int ldb,
    int N, int K, int mode,
    float* __restrict__ oq, float* __restrict__ okk, float* __restrict__ ov)
{
    extern __shared__ __nv_bfloat16 sm[];       // bf16 units, 16B-aligned
    uint32_t smb = smem_u32(sm);

    int t = threadIdx.x;
    int warp = t >> 5, lane = t & 31;
    int wm = (warp >> 2) * 80;                  // 0 or 80
    int wn = (warp & 3) * 16;                   // 0,16,32,48
    int qr = lane >> 2, qc2 = (lane & 3) * 2;
    int n0 = blockIdx.x * 64;

    float acc[5][2][4];
    #pragma unroll
    for (int i = 0; i < 5; i++)
        #pragma unroll
        for (int j = 0; j < 2; j++)
            #pragma unroll
            for (int r = 0; r < 4; r++) acc[i][j][r] = 0.f;

    int nK = K >> 5;                            // K/32 chunks
    int wrow = t >> 2, wko = (t & 3) * 8;       // W chunk per thread (256 = 64*4)
    int wn_row = n0 + wrow;
    uint32_t w_ok = (wn_row < N) ? 16u : 0u;
    const __nv_bfloat16* wsrc_row = W + (size_t)((wn_row < N) ? wn_row : (N - 1)) * ldw + wko;

    // ---- stage loader ----
    auto load_stage = [&](int stage, int ks) {
        int k0 = ks << 5;
        uint32_t a_base = smb + stage * A_STAGE_B;
        #pragma unroll
        for (int c = 0; c < 3; c++) {
            int idx = t + c * 256;
            if (idx < 640) {
                int row = idx >> 2, ko = (idx & 3) * 8;
                cp_async16(a_base + row * 80 + ko * 2,
                           A + (size_t)row * lda + k0 + ko, 16u);
            }
        }
        uint32_t w_base = smb + W_REGION_OFF + stage * W_STAGE_B;
        cp_async16(w_base + wrow * 80 + wko * 2, wsrc_row + k0, w_ok);
        cp_commit();
    };

    load_stage(0, 0);
    load_stage(1, 1);

    for (int ks = 0; ks < nK; ks++) {
        cp_wait1();
        __syncthreads();

        int stage = ks % GSTAGES;
        const __nv_bfloat16* as = sm + stage * (A_STAGE_B / 2);
        const __nv_bfloat16* ws = sm + (W_REGION_OFF / 2) + stage * (W_STAGE_B / 2);

        #pragma unroll
        for (int kk = 0; kk < 32; kk += 16) {
            uint32_t af[5][4];
            #pragma unroll
            for (int i = 0; i < 5; i++) {
                int r = wm + i * 16 + qr;
                af[i][0] = *(const uint32_t*)&as[(size_t)r * 40 + kk + qc2];
                af[i][1] = *(const uint32_t*)&as[(size_t)(r + 8) * 40 + kk + qc2];
                af[i][2] = *(const uint32_t*)&as[(size_t)r * 40 + kk + qc2 + 8];
                af[i][3] = *(const uint32_t*)&as[(size_t)(r + 8) * 40 + kk + qc2 + 8];
            }
            uint32_t bf[2][2];
            #pragma unroll
            for (int j = 0; j < 2; j++) {
                int rn = wn + j * 8 + qr;
                bf[j][0] = *(const uint32_t*)&ws[(size_t)rn * 40 + kk + qc2];
                bf[j][1] = *(const uint32_t*)&ws[(size_t)rn * 40 + kk + qc2 + 8];
            }
            #pragma unroll
            for (int i = 0; i < 5; i++)
                #pragma unroll
                for (int j = 0; j < 2; j++)
                    mma16816(acc[i][j], af[i], bf[j]);
        }
        __syncthreads();

        int next = ks + GSTAGES - 1;
        if (next < nK) load_stage(next % GSTAGES, next);
        else cp_commit();   // keep group count consistent
    }

    // ---- epilogue ----
    #pragma unroll
    for (int i = 0; i < 5; i++) {
        #pragma unroll
        for (int j = 0; j < 2; j++) {
            int nb = n0 + wn + j * 8 + qc2;
            #pragma unroll
            for (int h = 0; h < 2; h++) {
                int m = wm + i * 16 + qr + h * 8;   // always < 160
                #pragma unroll
                for (int c2 = 0; c2 < 2; c2++) {
                    int n = nb + c2;
                    if (n >= N) continue;
                    float v = acc[i][j][h * 2 + c2] + __ldg(&bias[n]);
                    if (mode == 1) {
                        v = fmaxf(v, 0.f);
                        OutB[(size_t)m * ldb + n] = __float2bfloat16(v);
                    } else if (mode == 2) {
                        int seg = (n >= 6148) ? 2 : (n >= 3074 ? 1 : 0);
                        int col = n - seg * 3074;
                        float* dst = (seg == 0) ? oq : (seg == 1 ? okk : ov);
                        dst[(size_t)m * KP + col] = v;
                    } else {
                        OutF[(size_t)m * ldo + n] = v;
                    }
                }
            }
        }
    }
}

// ================= attention ====================================================
__global__ __launch_bounds__(512) void k_attn2() {
    int q0 = blockIdx.x * 16;
    int b = q0 / N_;
    int w = threadIdx.x >> 5, lane = threadIdx.x & 31;
    int r = q0 + w;
    __shared__ float ssc[16][N_];

    const float4* qp = (const float4*)&g_q[(size_t)r*KP];
    float scale = rsqrtf((float)D_);

    for (int kn = 0; kn < N_; kn++) {
        const float4* kp = (const float4*)&g_k[(size_t)(b*N_ + kn)*KP];
        float acc = 0.f;
        for (int d4 = lane; d4 < KP/4; d4 += 32) {
            float4 qv = qp[d4], kv = kp[d4];
            acc += qv.x*kv.x + qv.y*kv.y + qv.z*kv.z + qv.w*kv.w;
        }
        #pragma unroll
        for (int o = 16; o > 0; o >>= 1) acc += __shfl_down_sync(0xffffffffu, acc, o);
        if (lane == 0) ssc[w][kn] = acc * scale;
    }
    __syncwarp();

    float mx = -1e30f;
    for (int i = lane; i < N_; i += 32) mx = fmaxf(mx, ssc[w][i]);
    #pragma unroll
    for (int o = 16; o > 0; o >>= 1) mx = fmaxf(mx, __shfl_xor_sync(0xffffffffu, mx, o));
    float s = 0.f;
    for (int i = lane; i < N_; i += 32) { float e = expf(ssc[w][i] - mx); ssc[w][i] = e; s += e; }
    #pragma unroll
    for (int o = 16; o > 0; o >>= 1) s += __shfl_xor_sync(0xffffffffu, s, o);
    float inv = 1.f / s;
    __syncwarp();
    for (int i = lane; i < N_; i += 32) ssc[w][i] *= inv;
    __syncwarp();

    __nv_bfloat162* op = (__nv_bfloat162*)&g_av_bf[(size_t)r*KP];
    const float4* vb = (const float4*)&g_v[(size_t)b*N_*KP];
    for (int d4 = lane; d4 < KP/4; d4 += 32) {
        float4 acc = make_float4(0.f, 0.f, 0.f, 0.f);
        #pragma unroll 4
        for (int k = 0; k < N_; k++) {
            float4 vv = vb[(size_t)k*(KP/4) + d4];
            float sck = ssc[w][k];
            acc.x += sck*vv.x; acc.y += sck*vv.y; acc.z += sck*vv.z; acc.w += sck*vv.w;
        }
        op[d4*2]   = __float22bfloat162_rn(make_float2(acc.x, acc.y));
        op[d4*2+1] = __float22bfloat162_rn(make_float2(acc.z, acc.w));
    }
}

// ================= layernorm (+residual) -> fp32 + bf16 ========================
__global__ void k_ln(const float* __restrict__ in0, const float* __restrict__ in1,
                     const float* __restrict__ g, const float* __restrict__ bta,
                     float* __restrict__ outF, __nv_bfloat16* __restrict__ outB) {
    int row = blockIdx.x;
    __shared__ float srow[D_];
    __shared__ float red[256];
    int t = threadIdx.x;
    float lsum = 0.f;
    for (int d = t; d < D_; d += 256) {
        float v = in0[(size_t)row*KP + d] + in1[(size_t)row*KP + d];
        srow[d] = v; lsum += v;
    }
    red[t] = lsum; __syncthreads();
    for (int s = 128; s >= 1; s >>= 1) { if (t < s) red[t] += red[t+s]; __syncthreads(); }
    float mean = red[0] * (1.f/(float)D_);
    __syncthreads();
    float lsq = 0.f;
    for (int d = t; d < D_; d += 256) { float u = srow[d] - mean; lsq += u*u; }
    red[t] = lsq; __syncthreads();
    for (int s = 128; s >= 1; s >>= 1) { if (t < s) red[t] += red[t+s]; __syncthreads(); }
    float rstd = rsqrtf(red[0] * (1.f/(float)D_) + 1e-5f);
    __syncthreads();
    for (int d = t; d < KP; d += 256) {
        float v = (d < D_) ? (g[d] * ((srow[d] - mean) * rstd) + bta[d]) : 0.f;
        outF[(size_t)row*KP + d] = v;
        outB[(size_t)row*KP + d] = __float2bfloat16(v);
    }
}

// ================= update =======================================================
__global__ void k_update(float* __restrict__ dout, int iter) {
    int row = blockIdx.x;
    const float* o = g_outp + (size_t)row*OUTD_;
    for (int c = threadIdx.x; c < C_; c += blockDim.x)
        g_preq[row*C_ + c] += o[c];
    if (threadIdx.x == 0) {
        float ny = fminf(fmaxf(g_curr[row*2]   + o[C_],   0.f), 223.f);
        float nx = fminf(fmaxf(g_curr[row*2+1] + o[C_+1], 0.f), 223.f);
        g_curr[row*2]   = ny;
        g_curr[row*2+1] = nx;
        dout[iter*(B_*N_*2) + row*2]     = ny;
        dout[iter*(B_*N_*2) + row*2 + 1] = nx;
    }
}

// ================= launch =======================================================
extern "C" void kernel_launch(void* const* d_in, const int* in_sizes, int n_in,
                              void* d_out, int out_size) {
    (void)in_sizes; (void)n_in; (void)out_size;
    const float* pre_f   = (const float*)d_in[0];
    const float* curr_f  = (const float*)d_in[1];
    const float* first_f = (const float*)d_in[2];
    const int*   prev_b  = (const int*)  d_in[3];
    const int*   first_b = (const int*)  d_in[4];
    const float* lng = (const float*)d_in[5];
    const float* lnb = (const float*)d_in[6];
    const float* ipw = (const float*)d_in[7];
    const float* ipb = (const float*)d_in[8];
    const float* opw = (const float*)d_in[9];
    const float* opb = (const float*)d_in[10];
    const float* n1g = (const float*)d_in[11];
    const float* n1b = (const float*)d_in[12];
    const float* l1w = (const float*)d_in[13];
    const float* l1b = (const float*)d_in[14];
    const float* l2w = (const float*)d_in[15];
    const float* l2b = (const float*)d_in[16];
    const float* n2g = (const float*)d_in[17];
    const float* n2b = (const float*)d_in[18];
    const float* ow  = (const float*)d_in[19];
    const float* ob  = (const float*)d_in[20];

    cudaFuncSetAttribute(k_gemm, cudaFuncAttributeMaxDynamicSharedMemorySize, GEMM_SMEM);

    __nv_bfloat16 *p_ipw, *p_opw, *p_l1w, *p_l2w, *p_oww;
    cudaGetSymbolAddress((void**)&p_ipw, g_ipw);
    cudaGetSymbolAddress((void**)&p_opw, g_opw);
    cudaGetSymbolAddress((void**)&p_l1w, g_l1w);
    cudaGetSymbolAddress((void**)&p_l2w, g_l2w);
    cudaGetSymbolAddress((void**)&p_oww, g_oww);

    float *p_tokens, *p_q, *p_k, *p_v, *p_aproj, *p_x, *p_ff, *p_x2, *p_outp;
    cudaGetSymbolAddress((void**)&p_tokens, g_tokens);
    cudaGetSymbolAddress((void**)&p_q,      g_q);
    cudaGetSymbolAddress((void**)&p_k,      g_k);
    cudaGetSymbolAddress((void**)&p_v,      g_v);
    cudaGetSymbolAddress((void**)&p_aproj,  g_aproj);
    cudaGetSymbolAddress((void**)&p_x,      g_x);
    cudaGetSymbolAddress((void**)&p_ff,     g_ff);
    cudaGetSymbolAddress((void**)&p_x2,     g_x2);
    cudaGetSymbolAddress((void**)&p_outp,   g_outp);

    __nv_bfloat16 *p_tokbf, *p_avbf, *p_xbf, *p_hbf, *p_x2bf;
    cudaGetSymbolAddress((void**)&p_tokbf, g_tok_bf);
    cudaGetSymbolAddress((void**)&p_avbf,  g_av_bf);
    cudaGetSymbolAddress((void**)&p_xbf,   g_x_bf);
    cudaGetSymbolAddress((void**)&p_hbf,   g_h_bf);
    cudaGetSymbolAddress((void**)&p_x2bf,  g_x2_bf);

    // prologue
    k_align<<<B_, 128>>>(prev_b, first_b);
    k_gather_pf<<<M_, 256>>>(pre_f, first_f, prev_b);
    k_pe<<<N_, 256>>>();
    k_zero_qkvpad<<<M_, 64>>>();
    k_w2bf<<<TD_,  256>>>(ipw, p_ipw, D_,   KP);
    k_w2bf<<<D_,   256>>>(opw, p_opw, D_,   KP);
    k_w2bf<<<DFF_, 256>>>(l1w, p_l1w, D_,   KP);
    k_w2bf<<<D_,   256>>>(l2w, p_l2w, DFF_, DFF_);
    k_w2bf<<<OUTD_,256>>>(ow,  p_oww, D_,   KP);

    int gqkv = (TD_  + 63) / 64;   // 145
    int gop  = (D_   + 63) / 64;   // 49
    int gl1  = (DFF_ + 63) / 64;   // 32
    int gout = (OUTD_+ 63) / 64;   // 17

    for (int it = 0; it < REFINE_; it++) {
        k_tokens<<<M_, 256>>>(curr_f, lng, lnb);
        k_gemm<<<gqkv, 256, GEMM_SMEM>>>(p_tokbf, KP, p_ipw, KP, ipb,
                                         nullptr, 0, nullptr, 0,
                                         TD_, KP, 2, p_q, p_k, p_v);
        k_attn2<<<M_/16, 512>>>();
        k_gemm<<<gop, 256, GEMM_SMEM>>>(p_avbf, KP, p_opw, KP, opb,
                                        p_aproj, KP, nullptr, 0,
                                        D_, KP, 0, nullptr, nullptr, nullptr);
        k_ln<<<M_, 256>>>(p_tokens, p_aproj, n1g, n1b, p_x, p_xbf);
        k_gemm<<<gl1, 256, GEMM_SMEM>>>(p_xbf, KP, p_l1w, KP, l1b,
                                        nullptr, 0, p_hbf, DFF_,
                                        DFF_, KP, 1, nullptr, nullptr, nullptr);
        k_gemm<<<gop, 256, GEMM_SMEM>>>(p_hbf, DFF_, p_l2w, DFF_, l2b,
                                        p_ff, KP, nullptr, 0,
                                        D_, DFF_, 0, nullptr, nullptr, nullptr);
        k_ln<<<M_, 256>>>(p_x, p_ff, n2g, n2b, p_x2, p_x2bf);
        k_gemm<<<gout, 256, GEMM_SMEM>>>(p_x2bf, KP, p_oww, KP, ob,
                                         p_outp, OUTD_, nullptr, 0,
                                         OUTD_, KP, 0, nullptr, nullptr, nullptr);
        k_update<<<M_, 256>>>((float*)d_out, it);
    }
}

// round 8
// speedup vs baseline: 3.2251x; 1.3094x over previous
#include <cuda_runtime.h>
#include <cuda_bf16.h>
#include <math.h>
#include <stdint.h>

#define B_    2
#define C_    1024
#define N_    80
#define D_    3074
#define KP    3136      // padded K (49 chunks of 64)
#define TD_   9222
#define DFF_  2048
#define OUTD_ 1026
#define M_    160
#define REFINE_ 3

#define KC_D   49       // chunks for K=3136
#define KC_F   32       // chunks for K=2048
#define CHA    20480    // A chunk bytes  (160*128)
#define CHW    8192     // W chunk bytes  (64*128)
#define N64_IP 145
#define N64_OP 49
#define N64_L1 32
#define N64_L2 49
#define N64_OW 17

// ---------------- chunked+swizzled bf16 weights --------------------------------
__device__ __nv_bfloat16 g_ipw[(size_t)KC_D*N64_IP*4096];
__device__ __nv_bfloat16 g_opw[(size_t)KC_D*N64_OP*4096];
__device__ __nv_bfloat16 g_l1w[(size_t)KC_D*N64_L1*4096];
__device__ __nv_bfloat16 g_l2w[(size_t)KC_F*N64_L2*4096];
__device__ __nv_bfloat16 g_oww[(size_t)KC_D*N64_OW*4096];

// ---------------- chunked+swizzled bf16 activations (GEMM A-side) --------------
__device__ __nv_bfloat16 g_tokc[(size_t)KC_D*10240];
__device__ __nv_bfloat16 g_avc [(size_t)KC_D*10240];
__device__ __nv_bfloat16 g_xc  [(size_t)KC_D*10240];
__device__ __nv_bfloat16 g_hc  [(size_t)KC_F*10240];
__device__ __nv_bfloat16 g_x2c [(size_t)KC_D*10240];

// ---------------- fp32 linear activations --------------------------------------
__device__ float g_preq  [M_*C_];
__device__ float g_firstq[M_*C_];
__device__ float g_pe    [N_*D_];
__device__ float g_curr  [M_*2];
__device__ int   g_firstal[M_*2];
__device__ float g_tokens[M_*KP];
__device__ float g_q     [M_*KP];
__device__ float g_k     [M_*KP];
__device__ float g_v     [M_*KP];
__device__ float g_aproj [M_*KP];
__device__ float g_x     [M_*KP];
__device__ float g_ff    [M_*KP];
__device__ float g_x2    [M_*KP];
__device__ float g_outp  [M_*OUTD_];

// ================= helpers =======================================================
__device__ __forceinline__ uint32_t smem_u32(const void* p) {
    uint32_t a;
    asm("{ .reg .u64 t; cvta.to.shared.u64 t, %1; cvt.u32.u64 %0, t; }" : "=r"(a) : "l"(p));
    return a;
}

#define SW128(bo) ((bo) ^ (((bo) >> 3) & 0x70))

__device__ __forceinline__ void mbar_init(uint32_t mbar, uint32_t cnt) {
    asm volatile("mbarrier.init.shared.b64 [%0], %1;" :: "r"(mbar), "r"(cnt) : "memory");
}
__device__ __forceinline__ void mbar_expect(uint32_t mbar, uint32_t bytes) {
    asm volatile("mbarrier.arrive.expect_tx.shared.b64 _, [%0], %1;"
                 :: "r"(mbar), "r"(bytes) : "memory");
}
__device__ __forceinline__ void mbar_wait(uint32_t mbar, uint32_t parity) {
    asm volatile(
        "{\n\t"
        ".reg .pred P1;\n\t"
        "LAB_%=:\n\t"
        "mbarrier.try_wait.parity.acquire.cta.shared::cta.b64 P1, [%0], %1, 0x989680;\n\t"
        "@P1 bra.uni DONE_%=;\n\t"
        "bra.uni LAB_%=;\n\t"
        "DONE_%=:\n\t"
        "}"
        :: "r"(mbar), "r"(parity) : "memory");
}
__device__ __forceinline__ void fence_async() {
    asm volatile("fence.proxy.async.shared::cta;" ::: "memory");
}
__device__ __forceinline__ void bulk_ld(uint32_t dst, const void* src, uint32_t bytes, uint32_t bar) {
    asm volatile(
        "cp.async.bulk.shared::cluster.global.mbarrier::complete_tx::bytes [%0], [%1], %2, [%3];"
        :: "r"(dst), "l"(src), "r"(bytes), "r"(bar) : "memory");
}
__device__ __forceinline__ void mma16816(float c[4], const uint32_t a[4], const uint32_t b[2]) {
    asm volatile(
        "mma.sync.aligned.m16n8k16.row.col.f32.bf16.bf16.f32 "
        "{%0,%1,%2,%3},{%4,%5,%6,%7},{%8,%9},{%0,%1,%2,%3};"
        : "+f"(c[0]), "+f"(c[1]), "+f"(c[2]), "+f"(c[3])
        : "r"(a[0]), "r"(a[1]), "r"(a[2]), "r"(a[3]), "r"(b[0]), "r"(b[1]));
}

// ================= bilinear sampling ============================================
struct Bil { int i0,i1,j0,j1; float w00,w01,w10,w11; };

__device__ __forceinline__ Bil make_bil(int py, int px) {
    float cy = ((float)py + 0.5f) * (14.0f/224.0f) - 0.5f;
    float cx = ((float)px + 0.5f) * (14.0f/224.0f) - 0.5f;
    float fy = floorf(cy), fx = floorf(cx);
    float ay = cy - fy,    ax = cx - fx;
    int y0 = (int)fy, x0 = (int)fx;
    Bil b;
    b.i0 = min(13, max(0, y0));   b.i1 = min(13, max(0, y0+1));
    b.j0 = min(13, max(0, x0));   b.j1 = min(13, max(0, x0+1));
    b.w00 = (1.f-ay)*(1.f-ax); b.w01 = (1.f-ay)*ax;
    b.w10 = ay*(1.f-ax);       b.w11 = ay*ax;
    return b;
}

__device__ __forceinline__ float bil_sample(const float* __restrict__ f, int c, const Bil& b) {
    const float* p = f + c*196;
    return b.w00*p[b.i0*14 + b.j0] + b.w01*p[b.i0*14 + b.j1]
         + b.w10*p[b.i1*14 + b.j0] + b.w11*p[b.i1*14 + b.j1];
}

// pack 8 floats -> uint4 of bf16
__device__ __forceinline__ uint4 pack8(const float* v) {
    uint4 r;
    __nv_bfloat162 b0 = __float22bfloat162_rn(make_float2(v[0], v[1]));
    __nv_bfloat162 b1 = __float22bfloat162_rn(make_float2(v[2], v[3]));
    __nv_bfloat162 b2 = __float22bfloat162_rn(make_float2(v[4], v[5]));
    __nv_bfloat162 b3 = __float22bfloat162_rn(make_float2(v[6], v[7]));
    r.x = *(uint32_t*)&b0; r.y = *(uint32_t*)&b1;
    r.z = *(uint32_t*)&b2; r.w = *(uint32_t*)&b3;
    return r;
}

// ================= prologue kernels =============================================
__global__ void k_align(const int* __restrict__ prev, const int* __restrict__ first) {
    int b = blockIdx.x;
    __shared__ int sp[N_*2], sf[N_*2];
    __shared__ int sdist[N_];
    __shared__ int sbest;
    int t = threadIdx.x;
    for (int i = t; i < N_*2; i += blockDim.x) {
        sp[i] = prev [b*N_*2 + i];
        sf[i] = first[b*N_*2 + i];
    }
    __syncthreads();
    for (int s = t; s < N_; s += blockDim.x) {
        int acc = 0;
        for (int j = 0; j < N_; j++) {
            int jj = (j - s + N_) % N_;
            acc += abs(sp[j*2]   - sf[jj*2]);
            acc += abs(sp[j*2+1] - sf[jj*2+1]);
        }
        sdist[s] = acc;
    }
    __syncthreads();
    if (t == 0) {
        int bd = sdist[0], bs = 0;
        for (int s = 1; s < N_; s++) if (sdist[s] < bd) { bd = sdist[s]; bs = s; }
        sbest = bs;
    }
    __syncthreads();
    int best = sbest;
    for (int j = t; j < N_; j += blockDim.x) {
        int jj = (j - best + N_) % N_;
        g_firstal[(b*N_ + j)*2]     = sf[jj*2];
        g_firstal[(b*N_ + j)*2 + 1] = sf[jj*2+1];
    }
}

__global__ void k_gather_pf(const float* __restrict__ pre_f,
                            const float* __restrict__ first_f,
                            const int* __restrict__ prev) {
    int row = blockIdx.x;
    int b = row / N_;
    int py = prev[row*2], px = prev[row*2+1];
    Bil bp = make_bil(py, px);
    Bil bf = make_bil(g_firstal[row*2], g_firstal[row*2+1]);
    const float* pf = pre_f   + b*C_*196;
    const float* ff = first_f + b*C_*196;
    for (int c = threadIdx.x; c < C_; c += blockDim.x) {
        g_preq  [row*C_ + c] = bil_sample(pf, c, bp);
        g_firstq[row*C_ + c] = bil_sample(ff, c, bf);
    }
    if (threadIdx.x < KP - D_) {   // zero q/k/v pad columns once
        g_q[(size_t)row*KP + D_ + threadIdx.x] = 0.f;
        g_k[(size_t)row*KP + D_ + threadIdx.x] = 0.f;
        g_v[(size_t)row*KP + D_ + threadIdx.x] = 0.f;
    }
    if (threadIdx.x == 0) {
        g_curr[row*2]   = (float)py;
        g_curr[row*2+1] = (float)px;
    }
}

__global__ void k_pe() {
    int n = blockIdx.x;
    for (int d = threadIdx.x; d < D_; d += blockDim.x) {
        int k2 = d & ~1;
        float div = expf((float)k2 * (-9.210340371976184f / (float)D_));
        float arg = (float)n * div;
        g_pe[n*D_ + d] = (d & 1) ? cosf(arg) : sinf(arg);
    }
}

// ---- merged weight conversion: fp32 -> chunked+swizzled bf16 -------------------
__global__ void k_wconv(const float* __restrict__ ipw, const float* __restrict__ opw,
                        const float* __restrict__ l1w, const float* __restrict__ l2w,
                        const float* __restrict__ oww) {
    int b = blockIdx.x;
    const float* src; __nv_bfloat16* dst;
    int N, K, KC, N64, n;
    if (b < 9280)       { n = b;         src = ipw; dst = g_ipw; N = TD_;  K = D_;   KC = KC_D; N64 = N64_IP; }
    else if (b < 12416) { n = b - 9280;  src = opw; dst = g_opw; N = D_;   K = D_;   KC = KC_D; N64 = N64_OP; }
    else if (b < 14464) { n = b - 12416; src = l1w; dst = g_l1w; N = DFF_; K = D_;   KC = KC_D; N64 = N64_L1; }
    else if (b < 17600) { n = b - 14464; src = l2w; dst = g_l2w; N = D_;   K = DFF_; KC = KC_F; N64 = N64_L2; }
    else                { n = b - 17600; src = oww; dst = g_oww; N = OUTD_;K = D_;   KC = KC_D; N64 = N64_OW; }

    bool nok = n < N;
    const float* srow = src + (size_t)n * K;
    char* dbase = (char*)dst + (size_t)(n >> 6) * CHW;
    uint32_t lrow = (uint32_t)((n & 63) * 128);
    size_t kstride = (size_t)N64 * CHW;
    int units = KC * 8;

    for (int u = threadIdx.x; u < units; u += 128) {
        int k0 = u * 8;
        float v[8];
        if (nok && k0 + 8 <= K) {
            float2 f0 = *(const float2*)(srow + k0);
            float2 f1 = *(const float2*)(srow + k0 + 2);
            float2 f2 = *(const float2*)(srow + k0 + 4);
            float2 f3 = *(const float2*)(srow + k0 + 6);
            v[0]=f0.x; v[1]=f0.y; v[2]=f1.x; v[3]=f1.y;
            v[4]=f2.x; v[5]=f2.y; v[6]=f3.x; v[7]=f3.y;
        } else {
            #pragma unroll
            for (int e = 0; e < 8; e++)
                v[e] = (nok && (k0 + e) < K) ? srow[k0 + e] : 0.f;
        }
        uint32_t loc = lrow + (uint32_t)((k0 & 63) * 2);
        *(uint4*)(dbase + (size_t)(k0 >> 6) * kstride + SW128(loc)) = pack8(v);
    }
}

// ================= tokens = LN(concat) + pe  (fp32 lin + chunked bf16) ==========
__global__ void k_tokens(const float* __restrict__ curr_f,
                         const float* __restrict__ lng,
                         const float* __restrict__ lnb) {
    int row = blockIdx.x;
    int b = row / N_, n = row % N_;
    __shared__ float srow[D_];
    __shared__ float red[256];
    int t = threadIdx.x;

    float cy = g_curr[row*2], cx = g_curr[row*2+1];
    int py = (int)cy, px = (int)cx;
    Bil bb = make_bil(py, px);
    const float* cf = curr_f + b*C_*196;

    float lsum = 0.f;
    for (int d = t; d < D_; d += 256) {
        float v;
        if      (d < C_)        v = g_preq[row*C_ + d];
        else if (d < 2*C_)      v = bil_sample(cf, d - C_, bb);
        else if (d == 2*C_)     v = cy;
        else if (d == 2*C_+1)   v = cx;
        else                    v = g_firstq[row*C_ + (d - (2*C_+2))];
        srow[d] = v;
        lsum += v;
    }
    red[t] = lsum; __syncthreads();
    for (int s = 128; s >= 1; s >>= 1) { if (t < s) red[t] += red[t+s]; __syncthreads(); }
    float mean = red[0] * (1.f/(float)D_);
    __syncthreads();

    float lsq = 0.f;
    for (int d = t; d < D_; d += 256) { float u = srow[d] - mean; lsq += u*u; }
    red[t] = lsq; __syncthreads();
    for (int s = 128; s >= 1; s >>= 1) { if (t < s) red[t] += red[t+s]; __syncthreads(); }
    float rstd = rsqrtf(red[0] * (1.f/(float)D_) + 1e-5f);
    __syncthreads();

    char* cbase = (char*)g_tokc;
    uint32_t lrow = (uint32_t)(row * 128);
    for (int u = t; u < KP/8; u += 256) {
        int d0 = u * 8;
        float v[8];
        #pragma unroll
        for (int e = 0; e < 8; e++) {
            int d = d0 + e;
            v[e] = (d < D_) ? (lng[d] * ((srow[d] - mean) * rstd) + lnb[d] + g_pe[n*D_ + d]) : 0.f;
        }
        // fp32 linear
        float4* fp = (float4*)&g_tokens[(size_t)row*KP + d0];
        fp[0] = make_float4(v[0], v[1], v[2], v[3]);
        fp[1] = make_float4(v[4], v[5], v[6], v[7]);
        // chunked swizzled bf16
        uint32_t loc = lrow + (uint32_t)((d0 & 63) * 2);
        *(uint4*)(cbase + (size_t)(d0 >> 6) * CHA + SW128(loc)) = pack8(v);
    }
}

// ================= GEMM: mma.sync + cp.async.bulk 3-stage pipeline ==============
// Out tile [160, 64] of A[160,K] @ W[N,K]^T + bias
// modes: 0 -> fp32 OutF; 1 -> relu + chunked bf16 OutBc; 2 -> qkv split fp32
#define NSTG 3
#define STAGE_B (CHA + CHW)                  // 28672
#define GEMM_SMEM (NSTG*STAGE_B + 64)        // 86080

__global__ __launch_bounds__(256) void k_gemm(
    const __nv_bfloat16* __restrict__ Ac,
    const __nv_bfloat16* __restrict__ Wc,
    int KC, int N64,
    const float* __restrict__ bias,
    float* __restrict__ OutF, int ldo,
    __nv_bfloat16* __restrict__ OutBc,
    int N, int mode,
    float* __restrict__ oq, float* __restrict__ okk, float* __restrict__ ov)
{
    extern __shared__ char sm[];
    uint32_t smb = smem_u32(sm);
    uint32_t mb = smb + NSTG * STAGE_B;

    int t = threadIdx.x;
    int warp = t >> 5, lane = t & 31;
    int wm = (warp >> 2) * 80;
    int wn = (warp & 3) * 16;
    int qr = lane >> 2, qc2 = (lane & 3) * 2;
    int nb = blockIdx.x, n0 = nb * 64;
    uint32_t rx = (uint32_t)(qr * 16);       // swizzle xor (row%8 == qr for all our rows)

    if (t == 0) {
        mbar_init(mb, 1); mbar_init(mb + 8, 1); mbar_init(mb + 16, 1);
        fence_async();
    }
    __syncthreads();

    float acc[5][2][4];
    #pragma unroll
    for (int i = 0; i < 5; i++)
        #pragma unroll
        for (int j = 0; j < 2; j++)
            #pragma unroll
            for (int r = 0; r < 4; r++) acc[i][j][r] = 0.f;

    if (t == 0) {
        #pragma unroll
        for (int p = 0; p < 2; p++) {
            uint32_t s = p, bar = mb + s*8;
            mbar_expect(bar, STAGE_B);
            bulk_ld(smb + s*STAGE_B,       (const char*)Ac + (size_t)p*CHA, CHA, bar);
            bulk_ld(smb + s*STAGE_B + CHA, (const char*)Wc + ((size_t)p*N64 + nb)*CHW, CHW, bar);
        }
    }

    for (int ks = 0; ks < KC; ks++) {
        int s = ks % NSTG;
        mbar_wait(mb + s*8, (uint32_t)((ks/NSTG) & 1));
        if (t == 0 && ks + 2 < KC) {
            int kn = ks + 2;
            uint32_t s2 = kn % NSTG, bar = mb + s2*8;
            mbar_expect(bar, STAGE_B);
            bulk_ld(smb + s2*STAGE_B,       (const char*)Ac + (size_t)kn*CHA, CHA, bar);
            bulk_ld(smb + s2*STAGE_B + CHA, (const char*)Wc + ((size_t)kn*N64 + nb)*CHW, CHW, bar);
        }
        const char* as = sm + s*STAGE_B;
        const char* ws = as + CHA;

        #pragma unroll
        for (int kk = 0; kk < 64; kk += 16) {
            uint32_t c0 = ((uint32_t)((kk + qc2) * 2)) ^ rx;
            uint32_t c1 = ((uint32_t)((kk + qc2) * 2 + 16)) ^ rx;
            uint32_t af[5][4];
            #pragma unroll
            for (int i = 0; i < 5; i++) {
                uint32_t r0 = (uint32_t)((wm + i*16 + qr) * 128);
                uint32_t r1 = r0 + 1024;
                af[i][0] = *(const uint32_t*)(as + r0 + c0);
                af[i][1] = *(const uint32_t*)(as + r1 + c0);
                af[i][2] = *(const uint32_t*)(as + r0 + c1);
                af[i][3] = *(const uint32_t*)(as + r1 + c1);
            }
            uint32_t bf[2][2];
            #pragma unroll
            for (int j = 0; j < 2; j++) {
                uint32_t rn = (uint32_t)((wn + j*8 + qr) * 128);
                bf[j][0] = *(const uint32_t*)(ws + rn + c0);
                bf[j][1] = *(const uint32_t*)(ws + rn + c1);
            }
            #pragma unroll
            for (int i = 0; i < 5; i++)
                #pragma unroll
                for (int j = 0; j < 2; j++)
                    mma16816(acc[i][j], af[i], bf[j]);
        }
        __syncthreads();
    }

    // ---- epilogue ----
    #pragma unroll
    for (int i = 0; i < 5; i++) {
        #pragma unroll
        for (int j = 0; j < 2; j++) {
            int nl = wn + j*8 + qc2;             // 0..63
            int n  = n0 + nl;
            #pragma unroll
            for (int h = 0; h < 2; h++) {
                int m = wm + i*16 + qr + h*8;
                float v0 = acc[i][j][h*2 + 0];
                float v1 = acc[i][j][h*2 + 1];
                if (mode == 1) {
                    v0 = fmaxf(v0 + __ldg(&bias[n]),     0.f);
                    v1 = fmaxf(v1 + __ldg(&bias[n + 1]), 0.f);
                    __nv_bfloat162 p = __float22bfloat162_rn(make_float2(v0, v1));
                    uint32_t loc = (uint32_t)(m * 128 + nl * 2);
                    *(__nv_bfloat162*)((char*)OutBc + (size_t)nb*CHA + SW128(loc)) = p;
                } else if (mode == 2) {
                    #pragma unroll
                    for (int c2 = 0; c2 < 2; c2++) {
                        int nn = n + c2;
                        if (nn >= TD_) continue;
                        float v = (c2 ? v1 : v0) + __ldg(&bias[nn]);
                        int seg = (nn >= 6148) ? 2 : (nn >= 3074 ? 1 : 0);
                        int col = nn - seg * 3074;
                        float* dst = (seg == 0) ? oq : (seg == 1 ? okk : ov);
                        dst[(size_t)m * KP + col] = v;
                    }
                } else {
                    #pragma unroll
                    for (int c2 = 0; c2 < 2; c2++) {
                        int nn = n + c2;
                        if (nn >= N) continue;
                        OutF[(size_t)m * ldo + nn] = (c2 ? v1 : v0) + __ldg(&bias[nn]);
                    }
                }
            }
        }
    }
}

// ================= attention (writes chunked av) ================================
__global__ __launch_bounds__(512) void k_attn2() {
    int q0 = blockIdx.x * 16;
    int b = q0 / N_;
    int w = threadIdx.x >> 5, lane = threadIdx.x & 31;
    int r = q0 + w;
    __shared__ float ssc[16][N_];

    const float4* qp = (const float4*)&g_q[(size_t)r*KP];
    float scale = rsqrtf((float)D_);

    for (int kn = 0; kn < N_; kn++) {
        const float4* kp = (const float4*)&g_k[(size_t)(b*N_ + kn)*KP];
        float acc = 0.f;
        for (int d4 = lane; d4 < KP/4; d4 += 32) {
            float4 qv = qp[d4], kv = kp[d4];
            acc += qv.x*kv.x + qv.y*kv.y + qv.z*kv.z + qv.w*kv.w;
        }
        #pragma unroll
        for (int o = 16; o > 0; o >>= 1) acc += __shfl_down_sync(0xffffffffu, acc, o);
        if (lane == 0) ssc[w][kn] = acc * scale;
    }
    __syncwarp();

    float mx = -1e30f;
    for (int i = lane; i < N_; i += 32) mx = fmaxf(mx, ssc[w][i]);
    #pragma unroll
    for (int o = 16; o > 0; o >>= 1) mx = fmaxf(mx, __shfl_xor_sync(0xffffffffu, mx, o));
    float s = 0.f;
    for (int i = lane; i < N_; i += 32) { float e = expf(ssc[w][i] - mx); ssc[w][i] = e; s += e; }
    #pragma unroll
    for (int o = 16; o > 0; o >>= 1) s += __shfl_xor_sync(0xffffffffu, s, o);
    float inv = 1.f / s;
    __syncwarp();
    for (int i = lane; i < N_; i += 32) ssc[w][i] *= inv;
    __syncwarp();

    char* cbase = (char*)g_avc;
    uint32_t lrow = (uint32_t)(r * 128);
    const float4* vb = (const float4*)&g_v[(size_t)b*N_*KP];
    for (int u = lane; u < KP/8; u += 32) {
        int d0 = u * 8;
        float a8[8] = {0.f,0.f,0.f,0.f,0.f,0.f,0.f,0.f};
        #pragma unroll 4
        for (int k = 0; k < N_; k++) {
            const float4* vp = vb + (size_t)k*(KP/4) + (d0 >> 2);
            float4 v0 = vp[0], v1 = vp[1];
            float sck = ssc[w][k];
            a8[0] += sck*v0.x; a8[1] += sck*v0.y; a8[2] += sck*v0.z; a8[3] += sck*v0.w;
            a8[4] += sck*v1.x; a8[5] += sck*v1.y; a8[6] += sck*v1.z; a8[7] += sck*v1.w;
        }
        uint32_t loc = lrow + (uint32_t)((d0 & 63) * 2);
        *(uint4*)(cbase + (size_t)(d0 >> 6) * CHA + SW128(loc)) = pack8(a8);
    }
}

// ================= layernorm (+residual) -> fp32 lin + chunked bf16 =============
__global__ void k_ln(const float* __restrict__ in0, const float* __restrict__ in1,
                     const float* __restrict__ g, const float* __restrict__ bta,
                     float* __restrict__ outF, __nv_bfloat16* __restrict__ outC) {
    int row = blockIdx.x;
    __shared__ float srow[D_];
    __shared__ float red[256];
    int t = threadIdx.x;
    float lsum = 0.f;
    for (int d = t; d < D_; d += 256) {
        float v = in0[(size_t)row*KP + d] + in1[(size_t)row*KP + d];
        srow[d] = v; lsum += v;
    }
    red[t] = lsum; __syncthreads();
    for (int s = 128; s >= 1; s >>= 1) { if (t < s) red[t] += red[t+s]; __syncthreads(); }
    float mean = red[0] * (1.f/(float)D_);
    __syncthreads();
    float lsq = 0.f;
    for (int d = t; d < D_; d += 256) { float u = srow[d] - mean; lsq += u*u; }
    red[t] = lsq; __syncthreads();
    for (int s = 128; s >= 1; s >>= 1) { if (t < s) red[t] += red[t+s]; __syncthreads(); }
    float rstd = rsqrtf(red[0] * (1.f/(float)D_) + 1e-5f);
    __syncthreads();

    char* cbase = (char*)outC;
    uint32_t lrow = (uint32_t)(row * 128);
    for (int u = t; u < KP/8; u += 256) {
        int d0 = u * 8;
        float v[8];
        #pragma unroll
        for (int e = 0; e < 8; e++) {
            int d = d0 + e;
            v[e] = (d < D_) ? (g[d] * ((srow[d] - mean) * rstd) + bta[d]) : 0.f;
        }
        float4* fp = (float4*)&outF[(size_t)row*KP + d0];
        fp[0] = make_float4(v[0], v[1], v[2], v[3]);
        fp[1] = make_float4(v[4], v[5], v[6], v[7]);
        uint32_t loc = lrow + (uint32_t)((d0 & 63) * 2);
        *(uint4*)(cbase + (size_t)(d0 >> 6) * CHA + SW128(loc)) = pack8(v);
    }
}

// ================= update =======================================================
__global__ void k_update(float* __restrict__ dout, int iter) {
    int row = blockIdx.x;
    const float* o = g_outp + (size_t)row*OUTD_;
    for (int c = threadIdx.x; c < C_; c += blockDim.x)
        g_preq[row*C_ + c] += o[c];
    if (threadIdx.x == 0) {
        float ny = fminf(fmaxf(g_curr[row*2]   + o[C_],   0.f), 223.f);
        float nx = fminf(fmaxf(g_curr[row*2+1] + o[C_+1], 0.f), 223.f);
        g_curr[row*2]   = ny;
        g_curr[row*2+1] = nx;
        dout[iter*(B_*N_*2) + row*2]     = ny;
        dout[iter*(B_*N_*2) + row*2 + 1] = nx;
    }
}

// ================= launch =======================================================
extern "C" void kernel_launch(void* const* d_in, const int* in_sizes, int n_in,
                              void* d_out, int out_size) {
    (void)in_sizes; (void)n_in; (void)out_size;
    const float* pre_f   = (const float*)d_in[0];
    const float* curr_f  = (const float*)d_in[1];
    const float* first_f = (const float*)d_in[2];
    const int*   prev_b  = (const int*)  d_in[3];
    const int*   first_b = (const int*)  d_in[4];
    const float* lng = (const float*)d_in[5];
    const float* lnb = (const float*)d_in[6];
    const float* ipw = (const float*)d_in[7];
    const float* ipb = (const float*)d_in[8];
    const float* opw = (const float*)d_in[9];
    const float* opb = (const float*)d_in[10];
    const float* n1g = (const float*)d_in[11];
    const float* n1b = (const float*)d_in[12];
    const float* l1w = (const float*)d_in[13];
    const float* l1b = (const float*)d_in[14];
    const float* l2w = (const float*)d_in[15];
    const float* l2b = (const float*)d_in[16];
    const float* n2g = (const float*)d_in[17];
    const float* n2b = (const float*)d_in[18];
    const float* ow  = (const float*)d_in[19];
    const float* ob  = (const float*)d_in[20];

    cudaFuncSetAttribute(k_gemm, cudaFuncAttributeMaxDynamicSharedMemorySize, GEMM_SMEM);

    __nv_bfloat16 *p_ipw, *p_opw, *p_l1w, *p_l2w, *p_oww;
    cudaGetSymbolAddress((void**)&p_ipw, g_ipw);
    cudaGetSymbolAddress((void**)&p_opw, g_opw);
    cudaGetSymbolAddress((void**)&p_l1w, g_l1w);
    cudaGetSymbolAddress((void**)&p_l2w, g_l2w);
    cudaGetSymbolAddress((void**)&p_oww, g_oww);

    float *p_tokens, *p_q, *p_k, *p_v, *p_aproj, *p_x, *p_ff, *p_x2, *p_outp;
    cudaGetSymbolAddress((void**)&p_tokens, g_tokens);
    cudaGetSymbolAddress((void**)&p_q,      g_q);
    cudaGetSymbolAddress((void**)&p_k,      g_k);
    cudaGetSymbolAddress((void**)&p_v,      g_v);
    cudaGetSymbolAddress((void**)&p_aproj,  g_aproj);
    cudaGetSymbolAddress((void**)&p_x,      g_x);
    cudaGetSymbolAddress((void**)&p_ff,     g_ff);
    cudaGetSymbolAddress((void**)&p_x2,     g_x2);
    cudaGetSymbolAddress((void**)&p_outp,   g_outp);

    __nv_bfloat16 *p_tokc, *p_avc, *p_xc, *p_hc, *p_x2c;
    cudaGetSymbolAddress((void**)&p_tokc, g_tokc);
    cudaGetSymbolAddress((void**)&p_avc,  g_avc);
    cudaGetSymbolAddress((void**)&p_xc,   g_xc);
    cudaGetSymbolAddress((void**)&p_hc,   g_hc);
    cudaGetSymbolAddress((void**)&p_x2c,  g_x2c);

    // prologue: launches 0..3 (so that launch #5 == qkv GEMM for ncu -s 5 -c 1)
    k_align<<<B_, 128>>>(prev_b, first_b);
    k_gather_pf<<<M_, 256>>>(pre_f, first_f, prev_b);
    k_pe<<<N_, 256>>>();
    k_wconv<<<18688, 128>>>(ipw, opw, l1w, l2w, ow);

    for (int it = 0; it < REFINE_; it++) {
        k_tokens<<<M_, 256>>>(curr_f, lng, lnb);
        k_gemm<<<N64_IP, 256, GEMM_SMEM>>>(p_tokc, p_ipw, KC_D, N64_IP, ipb,
                                           nullptr, 0, nullptr, TD_, 2, p_q, p_k, p_v);
        k_attn2<<<M_/16, 512>>>();
        k_gemm<<<N64_OP, 256, GEMM_SMEM>>>(p_avc, p_opw, KC_D, N64_OP, opb,
                                           p_aproj, KP, nullptr, D_, 0,
                                           nullptr, nullptr, nullptr);
        k_ln<<<M_, 256>>>(p_tokens, p_aproj, n1g, n1b, p_x, p_xc);
        k_gemm<<<N64_L1, 256, GEMM_SMEM>>>(p_xc, p_l1w, KC_D, N64_L1, l1b,
                                           nullptr, 0, p_hc, DFF_, 1,
                                           nullptr, nullptr, nullptr);
        k_gemm<<<N64_L2, 256, GEMM_SMEM>>>(p_hc, p_l2w, KC_F, N64_L2, l2b,
                                           p_ff, KP, nullptr, D_, 0,
                                           nullptr, nullptr, nullptr);
        k_ln<<<M_, 256>>>(p_x, p_ff, n2g, n2b, p_x2, p_x2c);
        k_gemm<<<N64_OW, 256, GEMM_SMEM>>>(p_x2c, p_oww, KC_D, N64_OW, ob,
                                           p_outp, OUTD_, nullptr, OUTD_, 0,
                                           nullptr, nullptr, nullptr);
        k_update<<<M_, 256>>>((float*)d_out, it);
    }
}

// round 9
// speedup vs baseline: 8.6593x; 2.6850x over previous
#include <cuda_runtime.h>
#include <cuda_bf16.h>
#include <math.h>
#include <stdint.h>

#define B_    2
#define C_    1024
#define N_    80
#define D_    3074
#define KP    3136      // padded K (49 chunks of 64)
#define TD_   9222
#define DFF_  2048
#define OUTD_ 1026
#define M_    160
#define REFINE_ 3

#define KC_D   49
#define KC_F   32
#define CHA    20480    // A chunk bytes  (160*128)
#define CHW    8192     // W chunk bytes  (64*128)
#define N64_IP 145
#define N64_OP 49
#define N64_L1 32
#define N64_L2 49
#define N64_OW 17

// ---------------- chunked+swizzled bf16 weights --------------------------------
__device__ __nv_bfloat16 g_ipw[(size_t)KC_D*N64_IP*4096];
__device__ __nv_bfloat16 g_opw[(size_t)KC_D*N64_OP*4096];
__device__ __nv_bfloat16 g_l1w[(size_t)KC_D*N64_L1*4096];
__device__ __nv_bfloat16 g_l2w[(size_t)KC_F*N64_L2*4096];
__device__ __nv_bfloat16 g_oww[(size_t)KC_D*N64_OW*4096];

// ---------------- chunked+swizzled bf16 activations (GEMM A-side) --------------
__device__ __nv_bfloat16 g_tokc[(size_t)KC_D*10240];
__device__ __nv_bfloat16 g_avc [(size_t)KC_D*10240];
__device__ __nv_bfloat16 g_xc  [(size_t)KC_D*10240];
__device__ __nv_bfloat16 g_hc  [(size_t)KC_F*10240];
__device__ __nv_bfloat16 g_x2c [(size_t)KC_D*10240];

// ---------------- fp32 linear activations --------------------------------------
__device__ float g_preq  [M_*C_];
__device__ float g_firstq[M_*C_];
__device__ float g_curr  [M_*2];
__device__ float g_tokens[M_*KP];
__device__ float g_q     [M_*KP];
__device__ float g_k     [M_*KP];
__device__ float g_v     [M_*KP];
__device__ float g_aproj [M_*KP];
__device__ float g_x     [M_*KP];
__device__ float g_ff    [M_*KP];
__device__ float g_x2    [M_*KP];
__device__ float g_outp  [M_*OUTD_];

// ================= helpers =======================================================
__device__ __forceinline__ uint32_t smem_u32(const void* p) {
    uint32_t a;
    asm("{ .reg .u64 t; cvta.to.shared.u64 t, %1; cvt.u32.u64 %0, t; }" : "=r"(a) : "l"(p));
    return a;
}

#define SW128(bo) ((bo) ^ (((bo) >> 3) & 0x70))

__device__ __forceinline__ void mbar_init(uint32_t mbar, uint32_t cnt) {
    asm volatile("mbarrier.init.shared.b64 [%0], %1;" :: "r"(mbar), "r"(cnt) : "memory");
}
__device__ __forceinline__ void mbar_expect(uint32_t mbar, uint32_t bytes) {
    asm volatile("mbarrier.arrive.expect_tx.shared.b64 _, [%0], %1;"
                 :: "r"(mbar), "r"(bytes) : "memory");
}
__device__ __forceinline__ void mbar_wait(uint32_t mbar, uint32_t parity) {
    asm volatile(
        "{\n\t"
        ".reg .pred P1;\n\t"
        "LAB_%=:\n\t"
        "mbarrier.try_wait.parity.acquire.cta.shared::cta.b64 P1, [%0], %1, 0x989680;\n\t"
        "@P1 bra.uni DONE_%=;\n\t"
        "bra.uni LAB_%=;\n\t"
        "DONE_%=:\n\t"
        "}"
        :: "r"(mbar), "r"(parity) : "memory");
}
__device__ __forceinline__ void fence_async() {
    asm volatile("fence.proxy.async.shared::cta;" ::: "memory");
}
__device__ __forceinline__ void bulk_ld(uint32_t dst, const void* src, uint32_t bytes, uint32_t bar) {
    asm volatile(
        "cp.async.bulk.shared::cluster.global.mbarrier::complete_tx::bytes [%0], [%1], %2, [%3];"
        :: "r"(dst), "l"(src), "r"(bytes), "r"(bar) : "memory");
}
__device__ __forceinline__ void ldsm4(uint32_t* r, uint32_t addr) {
    asm volatile("ldmatrix.sync.aligned.m8n8.x4.shared.b16 {%0,%1,%2,%3}, [%4];"
                 : "=r"(r[0]), "=r"(r[1]), "=r"(r[2]), "=r"(r[3]) : "r"(addr));
}
__device__ __forceinline__ void mma16816(float c[4], const uint32_t a[4],
                                         uint32_t b0, uint32_t b1) {
    asm volatile(
        "mma.sync.aligned.m16n8k16.row.col.f32.bf16.bf16.f32 "
        "{%0,%1,%2,%3},{%4,%5,%6,%7},{%8,%9},{%0,%1,%2,%3};"
        : "+f"(c[0]), "+f"(c[1]), "+f"(c[2]), "+f"(c[3])
        : "r"(a[0]), "r"(a[1]), "r"(a[2]), "r"(a[3]), "r"(b0), "r"(b1));
}

// ================= bilinear sampling ============================================
struct Bil { int i0,i1,j0,j1; float w00,w01,w10,w11; };

__device__ __forceinline__ Bil make_bil(int py, int px) {
    float cy = ((float)py + 0.5f) * (14.0f/224.0f) - 0.5f;
    float cx = ((float)px + 0.5f) * (14.0f/224.0f) - 0.5f;
    float fy = floorf(cy), fx = floorf(cx);
    float ay = cy - fy,    ax = cx - fx;
    int y0 = (int)fy, x0 = (int)fx;
    Bil b;
    b.i0 = min(13, max(0, y0));   b.i1 = min(13, max(0, y0+1));
    b.j0 = min(13, max(0, x0));   b.j1 = min(13, max(0, x0+1));
    b.w00 = (1.f-ay)*(1.f-ax); b.w01 = (1.f-ay)*ax;
    b.w10 = ay*(1.f-ax);       b.w11 = ay*ax;
    return b;
}

__device__ __forceinline__ float bil_sample(const float* __restrict__ f, int c, const Bil& b) {
    const float* p = f + c*196;
    return b.w00*p[b.i0*14 + b.j0] + b.w01*p[b.i0*14 + b.j1]
         + b.w10*p[b.i1*14 + b.j0] + b.w11*p[b.i1*14 + b.j1];
}

__device__ __forceinline__ uint4 pack8(const float* v) {
    uint4 r;
    __nv_bfloat162 b0 = __float22bfloat162_rn(make_float2(v[0], v[1]));
    __nv_bfloat162 b1 = __float22bfloat162_rn(make_float2(v[2], v[3]));
    __nv_bfloat162 b2 = __float22bfloat162_rn(make_float2(v[4], v[5]));
    __nv_bfloat162 b3 = __float22bfloat162_rn(make_float2(v[6], v[7]));
    r.x = *(uint32_t*)&b0; r.y = *(uint32_t*)&b1;
    r.z = *(uint32_t*)&b2; r.w = *(uint32_t*)&b3;
    return r;
}

// ================= weight conversion (launch #1) ================================
__global__ void k_wconv(const float* __restrict__ ipw, const float* __restrict__ opw,
                        const float* __restrict__ l1w, const float* __restrict__ l2w,
                        const float* __restrict__ oww) {
    int b = blockIdx.x;
    const float* src; __nv_bfloat16* dst;
    int N, K, KC, N64, n;
    if (b < 9280)       { n = b;         src = ipw; dst = g_ipw; N = TD_;  K = D_;   KC = KC_D; N64 = N64_IP; }
    else if (b < 12416) { n = b - 9280;  src = opw; dst = g_opw; N = D_;   K = D_;   KC = KC_D; N64 = N64_OP; }
    else if (b < 14464) { n = b - 12416; src = l1w; dst = g_l1w; N = DFF_; K = D_;   KC = KC_D; N64 = N64_L1; }
    else if (b < 17600) { n = b - 14464; src = l2w; dst = g_l2w; N = D_;   K = DFF_; KC = KC_F; N64 = N64_L2; }
    else                { n = b - 17600; src = oww; dst = g_oww; N = OUTD_;K = D_;   KC = KC_D; N64 = N64_OW; }

    bool nok = n < N;
    const float* srow = src + (size_t)n * K;
    char* dbase = (char*)dst + (size_t)(n >> 6) * CHW;
    uint32_t lrow = (uint32_t)((n & 63) * 128);
    size_t kstride = (size_t)N64 * CHW;
    int units = KC * 8;

    for (int u = threadIdx.x; u < units; u += 128) {
        int k0 = u * 8;
        float v[8];
        if (nok && k0 + 8 <= K) {
            float2 f0 = *(const float2*)(srow + k0);
            float2 f1 = *(const float2*)(srow + k0 + 2);
            float2 f2 = *(const float2*)(srow + k0 + 4);
            float2 f3 = *(const float2*)(srow + k0 + 6);
            v[0]=f0.x; v[1]=f0.y; v[2]=f1.x; v[3]=f1.y;
            v[4]=f2.x; v[5]=f2.y; v[6]=f3.x; v[7]=f3.y;
        } else {
            #pragma unroll
            for (int e = 0; e < 8; e++)
                v[e] = (nok && (k0 + e) < K) ? srow[k0 + e] : 0.f;
        }
        uint32_t loc = lrow + (uint32_t)((k0 & 63) * 2);
        *(uint4*)(dbase + (size_t)(k0 >> 6) * kstride + SW128(loc)) = pack8(v);
    }
}

// ================= gather (align inline; launch #2) =============================
__global__ void k_gather(const float* __restrict__ pre_f,
                         const float* __restrict__ first_f,
                         const int* __restrict__ prev,
                         const int* __restrict__ first) {
    int row = blockIdx.x;
    int b = row / N_, j = row % N_;
    __shared__ int sp[N_*2], sf[N_*2];
    __shared__ int skey[256];
    int t = threadIdx.x;
    for (int i = t; i < N_*2; i += 256) {
        sp[i] = prev [b*N_*2 + i];
        sf[i] = first[b*N_*2 + i];
    }
    __syncthreads();
    int key = 0x7FFFFFFF;
    if (t < N_) {
        int acc = 0;
        for (int q = 0; q < N_; q++) {
            int qq = (q - t + N_) % N_;
            acc += abs(sp[q*2]   - sf[qq*2]);
            acc += abs(sp[q*2+1] - sf[qq*2+1]);
        }
        key = acc * 128 + t;     // first-occurrence argmin (smaller shift wins ties)
    }
    skey[t] = key; __syncthreads();
    for (int s = 128; s >= 1; s >>= 1) {
        if (t < s) skey[t] = min(skey[t], skey[t+s]);
        __syncthreads();
    }
    int best = skey[0] & 127;

    int jj = (j - best + N_) % N_;
    int py = sp[j*2], px = sp[j*2+1];
    Bil bp = make_bil(py, px);
    Bil bf = make_bil(sf[jj*2], sf[jj*2+1]);
    const float* pf = pre_f   + b*C_*196;
    const float* ff = first_f + b*C_*196;
    for (int c = t; c < C_; c += 256) {
        g_preq  [row*C_ + c] = bil_sample(pf, c, bp);
        g_firstq[row*C_ + c] = bil_sample(ff, c, bf);
    }
    if (t < KP - D_) {
        g_q[(size_t)row*KP + D_ + t] = 0.f;
        g_k[(size_t)row*KP + D_ + t] = 0.f;
        g_v[(size_t)row*KP + D_ + t] = 0.f;
    }
    if (t == 0) {
        g_curr[row*2]   = (float)py;
        g_curr[row*2+1] = (float)px;
    }
}

// ================= tokens = LN(concat) + pe(inline)  (launch #3 in iter 0) ======
__global__ void k_tokens(const float* __restrict__ curr_f,
                         const float* __restrict__ lng,
                         const float* __restrict__ lnb) {
    int row = blockIdx.x;
    int b = row / N_, n = row % N_;
    __shared__ float srow[D_];
    __shared__ float red[256];
    int t = threadIdx.x;

    float cy = g_curr[row*2], cx = g_curr[row*2+1];
    int py = (int)cy, px = (int)cx;
    Bil bb = make_bil(py, px);
    const float* cf = curr_f + b*C_*196;

    float lsum = 0.f;
    for (int d = t; d < D_; d += 256) {
        float v;
        if      (d < C_)        v = g_preq[row*C_ + d];
        else if (d < 2*C_)      v = bil_sample(cf, d - C_, bb);
        else if (d == 2*C_)     v = cy;
        else if (d == 2*C_+1)   v = cx;
        else                    v = g_firstq[row*C_ + (d - (2*C_+2))];
        srow[d] = v;
        lsum += v;
    }
    red[t] = lsum; __syncthreads();
    for (int s = 128; s >= 1; s >>= 1) { if (t < s) red[t] += red[t+s]; __syncthreads(); }
    float mean = red[0] * (1.f/(float)D_);
    __syncthreads();

    float lsq = 0.f;
    for (int d = t; d < D_; d += 256) { float u = srow[d] - mean; lsq += u*u; }
    red[t] = lsq; __syncthreads();
    for (int s = 128; s >= 1; s >>= 1) { if (t < s) red[t] += red[t+s]; __syncthreads(); }
    float rstd = rsqrtf(red[0] * (1.f/(float)D_) + 1e-5f);
    __syncthreads();

    char* cbase = (char*)g_tokc;
    uint32_t lrow = (uint32_t)(row * 128);
    for (int u = t; u < KP/8; u += 256) {
        int d0 = u * 8;
        float v[8];
        #pragma unroll
        for (int e = 0; e < 8; e++) {
            int d = d0 + e;
            float pe = 0.f;
            if (d < D_) {
                int k2 = d & ~1;
                float div = expf((float)k2 * (-9.210340371976184f / (float)D_));
                float arg = (float)n * div;
                pe = (d & 1) ? cosf(arg) : sinf(arg);
            }
            v[e] = (d < D_) ? (lng[d] * ((srow[d] - mean) * rstd) + lnb[d] + pe) : 0.f;
        }
        float4* fp = (float4*)&g_tokens[(size_t)row*KP + d0];
        fp[0] = make_float4(v[0], v[1], v[2], v[3]);
        fp[1] = make_float4(v[4], v[5], v[6], v[7]);
        uint32_t loc = lrow + (uint32_t)((d0 & 63) * 2);
        *(uint4*)(cbase + (size_t)(d0 >> 6) * CHA + SW128(loc)) = pack8(v);
    }
}

// ================= GEMM: ldmatrix + mma.sync + cp.async.bulk ====================
#define NSTG 3
#define STAGE_B (CHA + CHW)
#define GEMM_SMEM (NSTG*STAGE_B + 64)

__global__ __launch_bounds__(256) void k_gemm(
    const __nv_bfloat16* __restrict__ Ac,
    const __nv_bfloat16* __restrict__ Wc,
    int KC, int N64,
    const float* __restrict__ bias,
    float* __restrict__ OutF, int ldo,
    __nv_bfloat16* __restrict__ OutBc,
    int N, int mode,
    float* __restrict__ oq, float* __restrict__ okk, float* __restrict__ ov)
{
    extern __shared__ char sm[];
    uint32_t smb = smem_u32(sm);
    uint32_t mb = smb + NSTG * STAGE_B;

    int t = threadIdx.x;
    int warp = t >> 5, lane = t & 31;
    int wm = (warp >> 2) * 80;
    int wn = (warp & 3) * 16;
    int qr = lane >> 2, qc2 = (lane & 3) * 2;
    int nb = blockIdx.x, n0 = nb * 64;

    // ldmatrix lane mapping
    int sub   = lane & 7;
    int m_off = ((lane >> 3) & 1) * 8 + sub;
    int k_off = (lane >> 4) * 8;
    uint32_t swz = (uint32_t)(sub * 16);

    if (t == 0) {
        mbar_init(mb, 1); mbar_init(mb + 8, 1); mbar_init(mb + 16, 1);
        fence_async();
    }
    __syncthreads();

    float acc[5][2][4];
    #pragma unroll
    for (int i = 0; i < 5; i++)
        #pragma unroll
        for (int j = 0; j < 2; j++)
            #pragma unroll
            for (int r = 0; r < 4; r++) acc[i][j][r] = 0.f;

    if (t == 0) {
        #pragma unroll
        for (int p = 0; p < 2; p++) {
            uint32_t s = p, bar = mb + s*8;
            mbar_expect(bar, STAGE_B);
            bulk_ld(smb + s*STAGE_B,       (const char*)Ac + (size_t)p*CHA, CHA, bar);
            bulk_ld(smb + s*STAGE_B + CHA, (const char*)Wc + ((size_t)p*N64 + nb)*CHW, CHW, bar);
        }
    }

    for (int ks = 0; ks < KC; ks++) {
        int s = ks % NSTG;
        mbar_wait(mb + s*8, (uint32_t)((ks/NSTG) & 1));
        if (t == 0 && ks + 2 < KC) {
            int kn = ks + 2;
            uint32_t s2 = kn % NSTG, bar = mb + s2*8;
            mbar_expect(bar, STAGE_B);
            bulk_ld(smb + s2*STAGE_B,       (const char*)Ac + (size_t)kn*CHA, CHA, bar);
            bulk_ld(smb + s2*STAGE_B + CHA, (const char*)Wc + ((size_t)kn*N64 + nb)*CHW, CHW, bar);
        }
        uint32_t as_b = smb + s*STAGE_B;
        uint32_t ws_b = as_b + CHA;

        #pragma unroll
        for (int kk = 0; kk < 64; kk += 16) {
            uint32_t col = ((uint32_t)((kk + k_off) * 2)) ^ swz;
            uint32_t am[5][4];
            #pragma unroll
            for (int i = 0; i < 5; i++)
                ldsm4(am[i], as_b + (uint32_t)((wm + i*16 + m_off) * 128) + col);
            uint32_t bm[4];
            ldsm4(bm, ws_b + (uint32_t)((wn + m_off) * 128) + col);
            #pragma unroll
            for (int i = 0; i < 5; i++) {
                mma16816(acc[i][0], am[i], bm[0], bm[2]);
                mma16816(acc[i][1], am[i], bm[1], bm[3]);
            }
        }
        __syncthreads();
    }

    // ---- epilogue ----
    #pragma unroll
    for (int i = 0; i < 5; i++) {
        #pragma unroll
        for (int j = 0; j < 2; j++) {
            int nl = wn + j*8 + qc2;
            int n  = n0 + nl;
            #pragma unroll
            for (int h = 0; h < 2; h++) {
                int m = wm + i*16 + qr + h*8;
                float v0 = acc[i][j][h*2 + 0];
                float v1 = acc[i][j][h*2 + 1];
                if (mode == 1) {
                    v0 = fmaxf(v0 + __ldg(&bias[n]),     0.f);
                    v1 = fmaxf(v1 + __ldg(&bias[n + 1]), 0.f);
                    __nv_bfloat162 p = __float22bfloat162_rn(make_float2(v0, v1));
                    uint32_t loc = (uint32_t)(m * 128 + nl * 2);
                    *(__nv_bfloat162*)((char*)OutBc + (size_t)nb*CHA + SW128(loc)) = p;
                } else if (mode == 2) {
                    #pragma unroll
                    for (int c2 = 0; c2 < 2; c2++) {
                        int nn = n + c2;
                        if (nn >= TD_) continue;
                        float v = (c2 ? v1 : v0) + __ldg(&bias[nn]);
                        int seg = (nn >= 6148) ? 2 : (nn >= 3074 ? 1 : 0);
                        int col = nn - seg * 3074;
                        float* dst = (seg == 0) ? oq : (seg == 1 ? okk : ov);
                        dst[(size_t)m * KP + col] = v;
                    }
                } else {
                    #pragma unroll
                    for (int c2 = 0; c2 < 2; c2++) {
                        int nn = n + c2;
                        if (nn >= N) continue;
                        OutF[(size_t)m * ldo + nn] = (c2 ? v1 : v0) + __ldg(&bias[nn]);
                    }
                }
            }
        }
    }
}

// ================= attention: one q-row per block ================================
__global__ __launch_bounds__(256) void k_attn2() {
    int r = blockIdx.x;
    int b = r / N_;
    int t = threadIdx.x, w = t >> 5, lane = t & 31;
    __shared__ float qs[KP];
    __shared__ float sc[N_];

    float4* qs4 = (float4*)qs;
    const float4* qp = (const float4*)&g_q[(size_t)r*KP];
    for (int u = t; u < KP/4; u += 256) qs4[u] = qp[u];
    __syncthreads();

    float scale = rsqrtf((float)D_);
    for (int kn = w; kn < N_; kn += 8) {
        const float4* kp = (const float4*)&g_k[(size_t)(b*N_ + kn)*KP];
        float acc = 0.f;
        for (int u = lane; u < KP/4; u += 32) {
            float4 a = qs4[u], c = kp[u];
            acc += a.x*c.x + a.y*c.y + a.z*c.z + a.w*c.w;
        }
        #pragma unroll
        for (int o = 16; o > 0; o >>= 1) acc += __shfl_down_sync(0xffffffffu, acc, o);
        if (lane == 0) sc[kn] = acc * scale;
    }
    __syncthreads();

    if (w == 0) {
        float v0 = (lane      < N_) ? sc[lane]      : -1e30f;
        float v1 = (lane + 32 < N_) ? sc[lane + 32] : -1e30f;
        float v2 = (lane + 64 < N_) ? sc[lane + 64] : -1e30f;
        float mx = fmaxf(v0, fmaxf(v1, v2));
        #pragma unroll
        for (int o = 16; o > 0; o >>= 1) mx = fmaxf(mx, __shfl_xor_sync(0xffffffffu, mx, o));
        float e0 = (lane      < N_) ? expf(v0 - mx) : 0.f;
        float e1 = (lane + 32 < N_) ? expf(v1 - mx) : 0.f;
        float e2 = (lane + 64 < N_) ? expf(v2 - mx) : 0.f;
        float s = e0 + e1 + e2;
        #pragma unroll
        for (int o = 16; o > 0; o >>= 1) s += __shfl_xor_sync(0xffffffffu, s, o);
        float inv = 1.f / s;
        if (lane      < N_) sc[lane]      = e0 * inv;
        if (lane + 32 < N_) sc[lane + 32] = e1 * inv;
        if (lane + 64 < N_) sc[lane + 64] = e2 * inv;
    }
    __syncthreads();

    char* cbase = (char*)g_avc;
    uint32_t lrow = (uint32_t)(r * 128);
    const float* vb = &g_v[(size_t)b*N_*KP];
    for (int gidx = t; gidx < KP/8; gidx += 256) {
        int d0 = gidx * 8;
        float a8[8] = {0.f,0.f,0.f,0.f,0.f,0.f,0.f,0.f};
        #pragma unroll 4
        for (int k = 0; k < N_; k++) {
            const float4* vp = (const float4*)(vb + (size_t)k*KP + d0);
            float4 v0 = vp[0], v1 = vp[1];
            float sck = sc[k];
            a8[0] += sck*v0.x; a8[1] += sck*v0.y; a8[2] += sck*v0.z; a8[3] += sck*v0.w;
            a8[4] += sck*v1.x; a8[5] += sck*v1.y; a8[6] += sck*v1.z; a8[7] += sck*v1.w;
        }
        uint32_t loc = lrow + (uint32_t)((d0 & 63) * 2);
        *(uint4*)(cbase + (size_t)(d0 >> 6) * CHA + SW128(loc)) = pack8(a8);
    }
}

// ================= layernorm (+residual) ========================================
__global__ void k_ln(const float* __restrict__ in0, const float* __restrict__ in1,
                     const float* __restrict__ g, const float* __restrict__ bta,
                     float* __restrict__ outF, __nv_bfloat16* __restrict__ outC) {
    int row = blockIdx.x;
    __shared__ float srow[D_];
    __shared__ float red[256];
    int t = threadIdx.x;
    float lsum = 0.f;
    for (int d = t; d < D_; d += 256) {
        float v = in0[(size_t)row*KP + d] + in1[(size_t)row*KP + d];
        srow[d] = v; lsum += v;
    }
    red[t] = lsum; __syncthreads();
    for (int s = 128; s >= 1; s >>= 1) { if (t < s) red[t] += red[t+s]; __syncthreads(); }
    float mean = red[0] * (1.f/(float)D_);
    __syncthreads();
    float lsq = 0.f;
    for (int d = t; d < D_; d += 256) { float u = srow[d] - mean; lsq += u*u; }
    red[t] = lsq; __syncthreads();
    for (int s = 128; s >= 1; s >>= 1) { if (t < s) red[t] += red[t+s]; __syncthreads(); }
    float rstd = rsqrtf(red[0] * (1.f/(float)D_) + 1e-5f);
    __syncthreads();

    char* cbase = (char*)outC;
    uint32_t lrow = (uint32_t)(row * 128);
    for (int u = t; u < KP/8; u += 256) {
        int d0 = u * 8;
        float v[8];
        #pragma unroll
        for (int e = 0; e < 8; e++) {
            int d = d0 + e;
            v[e] = (d < D_) ? (g[d] * ((srow[d] - mean) * rstd) + bta[d]) : 0.f;
        }
        float4* fp = (float4*)&outF[(size_t)row*KP + d0];
        fp[0] = make_float4(v[0], v[1], v[2], v[3]);
        fp[1] = make_float4(v[4], v[5], v[6], v[7]);
        uint32_t loc = lrow + (uint32_t)((d0 & 63) * 2);
        *(uint4*)(cbase + (size_t)(d0 >> 6) * CHA + SW128(loc)) = pack8(v);
    }
}

// ================= update =======================================================
__global__ void k_update(float* __restrict__ dout, int iter) {
    int row = blockIdx.x;
    const float* o = g_outp + (size_t)row*OUTD_;
    for (int c = threadIdx.x; c < C_; c += blockDim.x)
        g_preq[row*C_ + c] += o[c];
    if (threadIdx.x == 0) {
        float ny = fminf(fmaxf(g_curr[row*2]   + o[C_],   0.f), 223.f);
        float nx = fminf(fmaxf(g_curr[row*2+1] + o[C_+1], 0.f), 223.f);
        g_curr[row*2]   = ny;
        g_curr[row*2+1] = nx;
        dout[iter*(B_*N_*2) + row*2]     = ny;
        dout[iter*(B_*N_*2) + row*2 + 1] = nx;
    }
}

// ================= launch =======================================================
extern "C" void kernel_launch(void* const* d_in, const int* in_sizes, int n_in,
                              void* d_out, int out_size) {
    (void)in_sizes; (void)n_in; (void)out_size;
    const float* pre_f   = (const float*)d_in[0];
    const float* curr_f  = (const float*)d_in[1];
    const float* first_f = (const float*)d_in[2];
    const int*   prev_b  = (const int*)  d_in[3];
    const int*   first_b = (const int*)  d_in[4];
    const float* lng = (const float*)d_in[5];
    const float* lnb = (const float*)d_in[6];
    const float* ipw = (const float*)d_in[7];
    const float* ipb = (const float*)d_in[8];
    const float* opw = (const float*)d_in[9];
    const float* opb = (const float*)d_in[10];
    const float* n1g = (const float*)d_in[11];
    const float* n1b = (const float*)d_in[12];
    const float* l1w = (const float*)d_in[13];
    const float* l1b = (const float*)d_in[14];
    const float* l2w = (const float*)d_in[15];
    const float* l2b = (const float*)d_in[16];
    const float* n2g = (const float*)d_in[17];
    const float* n2b = (const float*)d_in[18];
    const float* ow  = (const float*)d_in[19];
    const float* ob  = (const float*)d_in[20];

    cudaFuncSetAttribute(k_gemm, cudaFuncAttributeMaxDynamicSharedMemorySize, GEMM_SMEM);

    __nv_bfloat16 *p_ipw, *p_opw, *p_l1w, *p_l2w, *p_oww;
    cudaGetSymbolAddress((void**)&p_ipw, g_ipw);
    cudaGetSymbolAddress((void**)&p_opw, g_opw);
    cudaGetSymbolAddress((void**)&p_l1w, g_l1w);
    cudaGetSymbolAddress((void**)&p_l2w, g_l2w);
    cudaGetSymbolAddress((void**)&p_oww, g_oww);

    float *p_tokens, *p_q, *p_k, *p_v, *p_aproj, *p_x, *p_ff, *p_x2, *p_outp;
    cudaGetSymbolAddress((void**)&p_tokens, g_tokens);
    cudaGetSymbolAddress((void**)&p_q,      g_q);
    cudaGetSymbolAddress((void**)&p_k,      g_k);
    cudaGetSymbolAddress((void**)&p_v,      g_v);
    cudaGetSymbolAddress((void**)&p_aproj,  g_aproj);
    cudaGetSymbolAddress((void**)&p_x,      g_x);
    cudaGetSymbolAddress((void**)&p_ff,     g_ff);
    cudaGetSymbolAddress((void**)&p_x2,     g_x2);
    cudaGetSymbolAddress((void**)&p_outp,   g_outp);

    __nv_bfloat16 *p_tokc, *p_avc, *p_xc, *p_hc, *p_x2c;
    cudaGetSymbolAddress((void**)&p_tokc, g_tokc);
    cudaGetSymbolAddress((void**)&p_avc,  g_avc);
    cudaGetSymbolAddress((void**)&p_xc,   g_xc);
    cudaGetSymbolAddress((void**)&p_hc,   g_hc);
    cudaGetSymbolAddress((void**)&p_x2c,  g_x2c);

    // launches 1-3 so launch #4 == qkv GEMM (ncu captures the 4th launch)
    k_wconv<<<18688, 128>>>(ipw, opw, l1w, l2w, ow);
    k_gather<<<M_, 256>>>(pre_f, first_f, prev_b, first_b);

    for (int it = 0; it < REFINE_; it++) {
        k_tokens<<<M_, 256>>>(curr_f, lng, lnb);
        k_gemm<<<N64_IP, 256, GEMM_SMEM>>>(p_tokc, p_ipw, KC_D, N64_IP, ipb,
                                           nullptr, 0, nullptr, TD_, 2, p_q, p_k, p_v);
        k_attn2<<<M_, 256>>>();
        k_gemm<<<N64_OP, 256, GEMM_SMEM>>>(p_avc, p_opw, KC_D, N64_OP, opb,
                                           p_aproj, KP, nullptr, D_, 0,
                                           nullptr, nullptr, nullptr);
        k_ln<<<M_, 256>>>(p_tokens, p_aproj, n1g, n1b, p_x, p_xc);
        k_gemm<<<N64_L1, 256, GEMM_SMEM>>>(p_xc, p_l1w, KC_D, N64_L1, l1b,
                                           nullptr, 0, p_hc, DFF_, 1,
                                           nullptr, nullptr, nullptr);
        k_gemm<<<N64_L2, 256, GEMM_SMEM>>>(p_hc, p_l2w, KC_F, N64_L2, l2b,
                                           p_ff, KP, nullptr, D_, 0,
                                           nullptr, nullptr, nullptr);
        k_ln<<<M_, 256>>>(p_x, p_ff, n2g, n2b, p_x2, p_x2c);
        k_gemm<<<N64_OW, 256, GEMM_SMEM>>>(p_x2c, p_oww, KC_D, N64_OW, ob,
                                           p_outp, OUTD_, nullptr, OUTD_, 0,
                                           nullptr, nullptr, nullptr);
        k_update<<<M_, 256>>>((float*)d_out, it);
    }
}

// round 10
// speedup vs baseline: 9.1995x; 1.0624x over previous
#include <cuda_runtime.h>
#include <cuda_bf16.h>
#include <math.h>
#include <stdint.h>

#define B_    2
#define C_    1024
#define N_    80
#define D_    3074
#define KP    3200      // padded K (50 chunks of 64; even for 128-wide stages)
#define TD_   9222
#define DFF_  2048
#define OUTD_ 1026
#define M_    160
#define REFINE_ 3

#define KC_D   50
#define KC_F   32
#define KS_D   25       // 128-wide stages
#define KS_F   16
#define CHA    20480    // A chunk bytes  (160*128)
#define CHW    8192     // W chunk bytes  (64*128)
#define N64_IP 145
#define N64_OP 49
#define N64_L1 32
#define N64_L2 49
#define N64_OW 17

// ---------------- chunked+swizzled bf16 weights --------------------------------
__device__ __nv_bfloat16 g_ipw[(size_t)KC_D*N64_IP*4096];
__device__ __nv_bfloat16 g_opw[(size_t)KC_D*N64_OP*4096];
__device__ __nv_bfloat16 g_l1w[(size_t)KC_D*N64_L1*4096];
__device__ __nv_bfloat16 g_l2w[(size_t)KC_F*N64_L2*4096];
__device__ __nv_bfloat16 g_oww[(size_t)KC_D*N64_OW*4096];

// ---------------- chunked+swizzled bf16 activations (GEMM A-side) --------------
__device__ __nv_bfloat16 g_tokc[(size_t)KC_D*10240];
__device__ __nv_bfloat16 g_avc [(size_t)KC_D*10240];
__device__ __nv_bfloat16 g_xc  [(size_t)KC_D*10240];
__device__ __nv_bfloat16 g_hc  [(size_t)KC_F*10240];
__device__ __nv_bfloat16 g_x2c [(size_t)KC_D*10240];

// ---------------- fp32 linear activations --------------------------------------
__device__ float g_preq  [M_*C_];
__device__ float g_firstq[M_*C_];
__device__ float g_curr  [M_*2];
__device__ float g_tokens[M_*KP];
__device__ float g_q     [M_*KP];
__device__ float g_k     [M_*KP];
__device__ float g_v     [M_*KP];
__device__ float g_aproj [M_*KP];
__device__ float g_x     [M_*KP];
__device__ float g_ff    [M_*KP];
__device__ float g_x2    [M_*KP];
__device__ float g_outp  [M_*OUTD_];

// ================= helpers =======================================================
__device__ __forceinline__ uint32_t smem_u32(const void* p) {
    uint32_t a;
    asm("{ .reg .u64 t; cvta.to.shared.u64 t, %1; cvt.u32.u64 %0, t; }" : "=r"(a) : "l"(p));
    return a;
}

#define SW128(bo) ((bo) ^ (((bo) >> 3) & 0x70))

__device__ __forceinline__ void mbar_init(uint32_t mbar, uint32_t cnt) {
    asm volatile("mbarrier.init.shared.b64 [%0], %1;" :: "r"(mbar), "r"(cnt) : "memory");
}
__device__ __forceinline__ void mbar_expect(uint32_t mbar, uint32_t bytes) {
    asm volatile("mbarrier.arrive.expect_tx.shared.b64 _, [%0], %1;"
                 :: "r"(mbar), "r"(bytes) : "memory");
}
__device__ __forceinline__ void mbar_wait(uint32_t mbar, uint32_t parity) {
    asm volatile(
        "{\n\t"
        ".reg .pred P1;\n\t"
        "LAB_%=:\n\t"
        "mbarrier.try_wait.parity.acquire.cta.shared::cta.b64 P1, [%0], %1, 0x989680;\n\t"
        "@P1 bra.uni DONE_%=;\n\t"
        "bra.uni LAB_%=;\n\t"
        "DONE_%=:\n\t"
        "}"
        :: "r"(mbar), "r"(parity) : "memory");
}
__device__ __forceinline__ void fence_async() {
    asm volatile("fence.proxy.async.shared::cta;" ::: "memory");
}
__device__ __forceinline__ void bulk_ld(uint32_t dst, const void* src, uint32_t bytes, uint32_t bar) {
    asm volatile(
        "cp.async.bulk.shared::cluster.global.mbarrier::complete_tx::bytes [%0], [%1], %2, [%3];"
        :: "r"(dst), "l"(src), "r"(bytes), "r"(bar) : "memory");
}
__device__ __forceinline__ void ldsm4(uint32_t* r, uint32_t addr) {
    asm volatile("ldmatrix.sync.aligned.m8n8.x4.shared.b16 {%0,%1,%2,%3}, [%4];"
                 : "=r"(r[0]), "=r"(r[1]), "=r"(r[2]), "=r"(r[3]) : "r"(addr));
}
__device__ __forceinline__ void mma16816(float c[4], const uint32_t a[4],
                                         uint32_t b0, uint32_t b1) {
    asm volatile(
        "mma.sync.aligned.m16n8k16.row.col.f32.bf16.bf16.f32 "
        "{%0,%1,%2,%3},{%4,%5,%6,%7},{%8,%9},{%0,%1,%2,%3};"
        : "+f"(c[0]), "+f"(c[1]), "+f"(c[2]), "+f"(c[3])
        : "r"(a[0]), "r"(a[1]), "r"(a[2]), "r"(a[3]), "r"(b0), "r"(b1));
}

// ================= bilinear sampling ============================================
struct Bil { int i0,i1,j0,j1; float w00,w01,w10,w11; };

__device__ __forceinline__ Bil make_bil(int py, int px) {
    float cy = ((float)py + 0.5f) * (14.0f/224.0f) - 0.5f;
    float cx = ((float)px + 0.5f) * (14.0f/224.0f) - 0.5f;
    float fy = floorf(cy), fx = floorf(cx);
    float ay = cy - fy,    ax = cx - fx;
    int y0 = (int)fy, x0 = (int)fx;
    Bil b;
    b.i0 = min(13, max(0, y0));   b.i1 = min(13, max(0, y0+1));
    b.j0 = min(13, max(0, x0));   b.j1 = min(13, max(0, x0+1));
    b.w00 = (1.f-ay)*(1.f-ax); b.w01 = (1.f-ay)*ax;
    b.w10 = ay*(1.f-ax);       b.w11 = ay*ax;
    return b;
}

__device__ __forceinline__ float bil_sample(const float* __restrict__ f, int c, const Bil& b) {
    const float* p = f + c*196;
    return b.w00*p[b.i0*14 + b.j0] + b.w01*p[b.i0*14 + b.j1]
         + b.w10*p[b.i1*14 + b.j0] + b.w11*p[b.i1*14 + b.j1];
}

__device__ __forceinline__ uint4 pack8(const float* v) {
    uint4 r;
    __nv_bfloat162 b0 = __float22bfloat162_rn(make_float2(v[0], v[1]));
    __nv_bfloat162 b1 = __float22bfloat162_rn(make_float2(v[2], v[3]));
    __nv_bfloat162 b2 = __float22bfloat162_rn(make_float2(v[4], v[5]));
    __nv_bfloat162 b3 = __float22bfloat162_rn(make_float2(v[6], v[7]));
    r.x = *(uint32_t*)&b0; r.y = *(uint32_t*)&b1;
    r.z = *(uint32_t*)&b2; r.w = *(uint32_t*)&b3;
    return r;
}

// ================= weight conversion (launch #1) ================================
__global__ void k_wconv(const float* __restrict__ ipw, const float* __restrict__ opw,
                        const float* __restrict__ l1w, const float* __restrict__ l2w,
                        const float* __restrict__ oww) {
    int b = blockIdx.x;
    const float* src; __nv_bfloat16* dst;
    int N, K, KC, N64, n;
    if (b < 9280)       { n = b;         src = ipw; dst = g_ipw; N = TD_;  K = D_;   KC = KC_D; N64 = N64_IP; }
    else if (b < 12416) { n = b - 9280;  src = opw; dst = g_opw; N = D_;   K = D_;   KC = KC_D; N64 = N64_OP; }
    else if (b < 14464) { n = b - 12416; src = l1w; dst = g_l1w; N = DFF_; K = D_;   KC = KC_D; N64 = N64_L1; }
    else if (b < 17600) { n = b - 14464; src = l2w; dst = g_l2w; N = D_;   K = DFF_; KC = KC_F; N64 = N64_L2; }
    else                { n = b - 17600; src = oww; dst = g_oww; N = OUTD_;K = D_;   KC = KC_D; N64 = N64_OW; }

    bool nok = n < N;
    const float* srow = src + (size_t)n * K;
    char* dbase = (char*)dst + (size_t)(n >> 6) * CHW;
    uint32_t lrow = (uint32_t)((n & 63) * 128);
    size_t kstride = (size_t)N64 * CHW;
    int units = KC * 8;

    for (int u = threadIdx.x; u < units; u += 128) {
        int k0 = u * 8;
        float v[8];
        if (nok && k0 + 8 <= K) {
            float2 f0 = *(const float2*)(srow + k0);
            float2 f1 = *(const float2*)(srow + k0 + 2);
            float2 f2 = *(const float2*)(srow + k0 + 4);
            float2 f3 = *(const float2*)(srow + k0 + 6);
            v[0]=f0.x; v[1]=f0.y; v[2]=f1.x; v[3]=f1.y;
            v[4]=f2.x; v[5]=f2.y; v[6]=f3.x; v[7]=f3.y;
        } else {
            #pragma unroll
            for (int e = 0; e < 8; e++)
                v[e] = (nok && (k0 + e) < K) ? srow[k0 + e] : 0.f;
        }
        uint32_t loc = lrow + (uint32_t)((k0 & 63) * 2);
        *(uint4*)(dbase + (size_t)(k0 >> 6) * kstride + SW128(loc)) = pack8(v);
    }
}

// ================= gather (align inline; launch #2) =============================
__global__ void k_gather(const float* __restrict__ pre_f,
                         const float* __restrict__ first_f,
                         const int* __restrict__ prev,
                         const int* __restrict__ first) {
    int row = blockIdx.x;
    int b = row / N_, j = row % N_;
    __shared__ int sp[N_*2], sf[N_*2];
    __shared__ int skey[256];
    int t = threadIdx.x;
    for (int i = t; i < N_*2; i += 256) {
        sp[i] = prev [b*N_*2 + i];
        sf[i] = first[b*N_*2 + i];
    }
    __syncthreads();
    int key = 0x7FFFFFFF;
    if (t < N_) {
        int acc = 0;
        for (int q = 0; q < N_; q++) {
            int qq = (q - t + N_) % N_;
            acc += abs(sp[q*2]   - sf[qq*2]);
            acc += abs(sp[q*2+1] - sf[qq*2+1]);
        }
        key = acc * 128 + t;
    }
    skey[t] = key; __syncthreads();
    for (int s = 128; s >= 1; s >>= 1) {
        if (t < s) skey[t] = min(skey[t], skey[t+s]);
        __syncthreads();
    }
    int best = skey[0] & 127;

    int jj = (j - best + N_) % N_;
    int py = sp[j*2], px = sp[j*2+1];
    Bil bp = make_bil(py, px);
    Bil bf = make_bil(sf[jj*2], sf[jj*2+1]);
    const float* pf = pre_f   + b*C_*196;
    const float* ff = first_f + b*C_*196;
    for (int c = t; c < C_; c += 256) {
        g_preq  [row*C_ + c] = bil_sample(pf, c, bp);
        g_firstq[row*C_ + c] = bil_sample(ff, c, bf);
    }
    if (t < KP - D_) {
        g_q[(size_t)row*KP + D_ + t] = 0.f;
        g_k[(size_t)row*KP + D_ + t] = 0.f;
        g_v[(size_t)row*KP + D_ + t] = 0.f;
    }
    if (t == 0) {
        g_curr[row*2]   = (float)py;
        g_curr[row*2+1] = (float)px;
    }
}

// ================= tokens = LN(concat) + pe(inline) =============================
__global__ void k_tokens(const float* __restrict__ curr_f,
                         const float* __restrict__ lng,
                         const float* __restrict__ lnb) {
    int row = blockIdx.x;
    int b = row / N_, n = row % N_;
    __shared__ float srow[D_];
    __shared__ float red[256];
    int t = threadIdx.x;

    float cy = g_curr[row*2], cx = g_curr[row*2+1];
    int py = (int)cy, px = (int)cx;
    Bil bb = make_bil(py, px);
    const float* cf = curr_f + b*C_*196;

    float lsum = 0.f;
    for (int d = t; d < D_; d += 256) {
        float v;
        if      (d < C_)        v = g_preq[row*C_ + d];
        else if (d < 2*C_)      v = bil_sample(cf, d - C_, bb);
        else if (d == 2*C_)     v = cy;
        else if (d == 2*C_+1)   v = cx;
        else                    v = g_firstq[row*C_ + (d - (2*C_+2))];
        srow[d] = v;
        lsum += v;
    }
    red[t] = lsum; __syncthreads();
    for (int s = 128; s >= 1; s >>= 1) { if (t < s) red[t] += red[t+s]; __syncthreads(); }
    float mean = red[0] * (1.f/(float)D_);
    __syncthreads();

    float lsq = 0.f;
    for (int d = t; d < D_; d += 256) { float u = srow[d] - mean; lsq += u*u; }
    red[t] = lsq; __syncthreads();
    for (int s = 128; s >= 1; s >>= 1) { if (t < s) red[t] += red[t+s]; __syncthreads(); }
    float rstd = rsqrtf(red[0] * (1.f/(float)D_) + 1e-5f);
    __syncthreads();

    char* cbase = (char*)g_tokc;
    uint32_t lrow = (uint32_t)(row * 128);
    for (int u = t; u < KP/8; u += 256) {
        int d0 = u * 8;
        float v[8];
        #pragma unroll
        for (int e = 0; e < 8; e++) {
            int d = d0 + e;
            float pe = 0.f;
            if (d < D_) {
                int k2 = d & ~1;
                float div = expf((float)k2 * (-9.210340371976184f / (float)D_));
                float arg = (float)n * div;
                pe = (d & 1) ? cosf(arg) : sinf(arg);
            }
            v[e] = (d < D_) ? (lng[d] * ((srow[d] - mean) * rstd) + lnb[d] + pe) : 0.f;
        }
        float4* fp = (float4*)&g_tokens[(size_t)row*KP + d0];
        fp[0] = make_float4(v[0], v[1], v[2], v[3]);
        fp[1] = make_float4(v[4], v[5], v[6], v[7]);
        uint32_t loc = lrow + (uint32_t)((d0 & 63) * 2);
        *(uint4*)(cbase + (size_t)(d0 >> 6) * CHA + SW128(loc)) = pack8(v);
    }
}

// ================= GEMM: 128-wide stages, reg-double-buffered fragments =========
#define NSTG 3
#define STAGE_B (2*CHA + 2*CHW)              // 57344
#define GEMM_SMEM (NSTG*STAGE_B + 64)        // 172096

__global__ __launch_bounds__(256) void k_gemm(
    const __nv_bfloat16* __restrict__ Ac,
    const __nv_bfloat16* __restrict__ Wc,
    int KS, int N64,
    const float* __restrict__ bias,
    float* __restrict__ OutF, int ldo,
    __nv_bfloat16* __restrict__ OutBc,
    int N, int mode,
    float* __restrict__ oq, float* __restrict__ okk, float* __restrict__ ov)
{
    extern __shared__ char sm[];
    uint32_t smb = smem_u32(sm);
    uint32_t mb = smb + NSTG * STAGE_B;

    int t = threadIdx.x;
    int warp = t >> 5, lane = t & 31;
    int wm = (warp >> 2) * 80;
    int wn = (warp & 3) * 16;
    int qr = lane >> 2, qc2 = (lane & 3) * 2;
    int nb = blockIdx.x, n0 = nb * 64;

    int sub   = lane & 7;
    int m_off = ((lane >> 3) & 1) * 8 + sub;
    int k_off = (lane >> 4) * 8;
    uint32_t swz = (uint32_t)(sub * 16);

    uint32_t a_row_off = 0;   // precomputed per-warp ldsm bases
    uint32_t w_row_off = (uint32_t)((wn + m_off) * 128);
    (void)a_row_off;

    if (t == 0) {
        mbar_init(mb, 1); mbar_init(mb + 8, 1); mbar_init(mb + 16, 1);
        fence_async();
    }
    __syncthreads();

    float acc[5][2][4];
    #pragma unroll
    for (int i = 0; i < 5; i++)
        #pragma unroll
        for (int j = 0; j < 2; j++)
            #pragma unroll
            for (int r = 0; r < 4; r++) acc[i][j][r] = 0.f;

    if (t == 0) {
        #pragma unroll
        for (int p = 0; p < 2; p++) {
            uint32_t s = p, bar = mb + s*8;
            mbar_expect(bar, STAGE_B);
            bulk_ld(smb + s*STAGE_B, (const char*)Ac + (size_t)(2*p)*CHA, 2*CHA, bar);
            bulk_ld(smb + s*STAGE_B + 2*CHA,
                    (const char*)Wc + ((size_t)(2*p)*N64 + nb)*CHW, CHW, bar);
            bulk_ld(smb + s*STAGE_B + 2*CHA + CHW,
                    (const char*)Wc + ((size_t)(2*p+1)*N64 + nb)*CHW, CHW, bar);
        }
    }

    uint32_t amA[5][4], bmA[4], amB[5][4], bmB[4];

    for (int ks = 0; ks < KS; ks++) {
        int s = ks % NSTG;
        mbar_wait(mb + s*8, (uint32_t)((ks/NSTG) & 1));
        if (t == 0 && ks + 2 < KS) {
            int kn = ks + 2;
            uint32_t s2 = kn % NSTG, bar = mb + s2*8;
            mbar_expect(bar, STAGE_B);
            bulk_ld(smb + s2*STAGE_B, (const char*)Ac + (size_t)(2*kn)*CHA, 2*CHA, bar);
            bulk_ld(smb + s2*STAGE_B + 2*CHA,
                    (const char*)Wc + ((size_t)(2*kn)*N64 + nb)*CHW, CHW, bar);
            bulk_ld(smb + s2*STAGE_B + 2*CHA + CHW,
                    (const char*)Wc + ((size_t)(2*kn+1)*N64 + nb)*CHW, CHW, bar);
        }
        uint32_t st_b = smb + s*STAGE_B;

        // 8 sub-steps: p = c2*4 + kki; c2 selects 64-K sub-chunk, kki selects 16-K slice
        // load(p) into A/B register buffers alternately; mma one step behind.
        #define LDP(BUFam, BUFbm, p) do { \
            int c2_ = (p) >> 2, kk_ = ((p) & 3) * 16; \
            uint32_t as_ = st_b + (uint32_t)(c2_ * CHA); \
            uint32_t ws_ = st_b + (uint32_t)(2*CHA + c2_ * CHW); \
            uint32_t col_ = ((uint32_t)((kk_ + k_off) * 2)) ^ swz; \
            ldsm4(BUFam[0], as_ + (uint32_t)((wm +   0 + m_off) * 128) + col_); \
            ldsm4(BUFam[1], as_ + (uint32_t)((wm +  16 + m_off) * 128) + col_); \
            ldsm4(BUFam[2], as_ + (uint32_t)((wm +  32 + m_off) * 128) + col_); \
            ldsm4(BUFam[3], as_ + (uint32_t)((wm +  48 + m_off) * 128) + col_); \
            ldsm4(BUFam[4], as_ + (uint32_t)((wm +  64 + m_off) * 128) + col_); \
            ldsm4(BUFbm,    ws_ + w_row_off + col_); \
        } while (0)

        #define MMAP(BUFam, BUFbm) do { \
            _Pragma("unroll") \
            for (int i_ = 0; i_ < 5; i_++) { \
                mma16816(acc[i_][0], BUFam[i_], BUFbm[0], BUFbm[2]); \
                mma16816(acc[i_][1], BUFam[i_], BUFbm[1], BUFbm[3]); \
            } \
        } while (0)

        LDP(amA, bmA, 0);
        #pragma unroll
        for (int p = 0; p < 8; p += 2) {
            if (p + 1 < 8) LDP(amB, bmB, p + 1);
            MMAP(amA, bmA);
            if (p + 2 < 8) LDP(amA, bmA, p + 2);
            MMAP(amB, bmB);
        }
        #undef LDP
        #undef MMAP
        __syncthreads();
    }

    // ---- epilogue ----
    #pragma unroll
    for (int i = 0; i < 5; i++) {
        #pragma unroll
        for (int j = 0; j < 2; j++) {
            int nl = wn + j*8 + qc2;
            int n  = n0 + nl;
            #pragma unroll
            for (int h = 0; h < 2; h++) {
                int m = wm + i*16 + qr + h*8;
                float v0 = acc[i][j][h*2 + 0];
                float v1 = acc[i][j][h*2 + 1];
                if (mode == 1) {
                    v0 = fmaxf(v0 + __ldg(&bias[n]),     0.f);
                    v1 = fmaxf(v1 + __ldg(&bias[n + 1]), 0.f);
                    __nv_bfloat162 p = __float22bfloat162_rn(make_float2(v0, v1));
                    uint32_t loc = (uint32_t)(m * 128 + nl * 2);
                    *(__nv_bfloat162*)((char*)OutBc + (size_t)nb*CHA + SW128(loc)) = p;
                } else if (mode == 2) {
                    #pragma unroll
                    for (int c2 = 0; c2 < 2; c2++) {
                        int nn = n + c2;
                        if (nn >= TD_) continue;
                        float v = (c2 ? v1 : v0) + __ldg(&bias[nn]);
                        int seg = (nn >= 6148) ? 2 : (nn >= 3074 ? 1 : 0);
                        int col = nn - seg * 3074;
                        float* dst = (seg == 0) ? oq : (seg == 1 ? okk : ov);
                        dst[(size_t)m * KP + col] = v;
                    }
                } else {
                    #pragma unroll
                    for (int c2 = 0; c2 < 2; c2++) {
                        int nn = n + c2;
                        if (nn >= N) continue;
                        OutF[(size_t)m * ldo + nn] = (c2 ? v1 : v0) + __ldg(&bias[nn]);
                    }
                }
            }
        }
    }
}

// ================= attention: one q-row per block ================================
__global__ __launch_bounds__(256) void k_attn2() {
    int r = blockIdx.x;
    int b = r / N_;
    int t = threadIdx.x, w = t >> 5, lane = t & 31;
    __shared__ float qs[KP];
    __shared__ float sc[N_];

    float4* qs4 = (float4*)qs;
    const float4* qp = (const float4*)&g_q[(size_t)r*KP];
    for (int u = t; u < KP/4; u += 256) qs4[u] = qp[u];
    __syncthreads();

    float scale = rsqrtf((float)D_);
    for (int kn = w; kn < N_; kn += 8) {
        const float4* kp = (const float4*)&g_k[(size_t)(b*N_ + kn)*KP];
        float acc = 0.f;
        for (int u = lane; u < KP/4; u += 32) {
            float4 a = qs4[u], c = kp[u];
            acc += a.x*c.x + a.y*c.y + a.z*c.z + a.w*c.w;
        }
        #pragma unroll
        for (int o = 16; o > 0; o >>= 1) acc += __shfl_down_sync(0xffffffffu, acc, o);
        if (lane == 0) sc[kn] = acc * scale;
    }
    __syncthreads();

    if (w == 0) {
        float v0 = (lane      < N_) ? sc[lane]      : -1e30f;
        float v1 = (lane + 32 < N_) ? sc[lane + 32] : -1e30f;
        float v2 = (lane + 64 < N_) ? sc[lane + 64] : -1e30f;
        float mx = fmaxf(v0, fmaxf(v1, v2));
        #pragma unroll
        for (int o = 16; o > 0; o >>= 1) mx = fmaxf(mx, __shfl_xor_sync(0xffffffffu, mx, o));
        float e0 = (lane      < N_) ? expf(v0 - mx) : 0.f;
        float e1 = (lane + 32 < N_) ? expf(v1 - mx) : 0.f;
        float e2 = (lane + 64 < N_) ? expf(v2 - mx) : 0.f;
        float s = e0 + e1 + e2;
        #pragma unroll
        for (int o = 16; o > 0; o >>= 1) s += __shfl_xor_sync(0xffffffffu, s, o);
        float inv = 1.f / s;
        if (lane      < N_) sc[lane]      = e0 * inv;
        if (lane + 32 < N_) sc[lane + 32] = e1 * inv;
        if (lane + 64 < N_) sc[lane + 64] = e2 * inv;
    }
    __syncthreads();

    char* cbase = (char*)g_avc;
    uint32_t lrow = (uint32_t)(r * 128);
    const float* vb = &g_v[(size_t)b*N_*KP];
    for (int gidx = t; gidx < KP/8; gidx += 256) {
        int d0 = gidx * 8;
        float a8[8] = {0.f,0.f,0.f,0.f,0.f,0.f,0.f,0.f};
        #pragma unroll 4
        for (int k = 0; k < N_; k++) {
            const float4* vp = (const float4*)(vb + (size_t)k*KP + d0);
            float4 v0 = vp[0], v1 = vp[1];
            float sck = sc[k];
            a8[0] += sck*v0.x; a8[1] += sck*v0.y; a8[2] += sck*v0.z; a8[3] += sck*v0.w;
            a8[4] += sck*v1.x; a8[5] += sck*v1.y; a8[6] += sck*v1.z; a8[7] += sck*v1.w;
        }
        uint32_t loc = lrow + (uint32_t)((d0 & 63) * 2);
        *(uint4*)(cbase + (size_t)(d0 >> 6) * CHA + SW128(loc)) = pack8(a8);
    }
}

// ================= layernorm (+residual) ========================================
__global__ void k_ln(const float* __restrict__ in0, const float* __restrict__ in1,
                     const float* __restrict__ g, const float* __restrict__ bta,
                     float* __restrict__ outF, __nv_bfloat16* __restrict__ outC) {
    int row = blockIdx.x;
    __shared__ float srow[D_];
    __shared__ float red[256];
    int t = threadIdx.x;
    float lsum = 0.f;
    for (int d = t; d < D_; d += 256) {
        float v = in0[(size_t)row*KP + d] + in1[(size_t)row*KP + d];
        srow[d] = v; lsum += v;
    }
    red[t] = lsum; __syncthreads();
    for (int s = 128; s >= 1; s >>= 1) { if (t < s) red[t] += red[t+s]; __syncthreads(); }
    float mean = red[0] * (1.f/(float)D_);
    __syncthreads();
    float lsq = 0.f;
    for (int d = t; d < D_; d += 256) { float u = srow[d] - mean; lsq += u*u; }
    red[t] = lsq; __syncthreads();
    for (int s = 128; s >= 1; s >>= 1) { if (t < s) red[t] += red[t+s]; __syncthreads(); }
    float rstd = rsqrtf(red[0] * (1.f/(float)D_) + 1e-5f);
    __syncthreads();

    char* cbase = (char*)outC;
    uint32_t lrow = (uint32_t)(row * 128);
    for (int u = t; u < KP/8; u += 256) {
        int d0 = u * 8;
        float v[8];
        #pragma unroll
        for (int e = 0; e < 8; e++) {
            int d = d0 + e;
            v[e] = (d < D_) ? (g[d] * ((srow[d] - mean) * rstd) + bta[d]) : 0.f;
        }
        float4* fp = (float4*)&outF[(size_t)row*KP + d0];
        fp[0] = make_float4(v[0], v[1], v[2], v[3]);
        fp[1] = make_float4(v[4], v[5], v[6], v[7]);
        uint32_t loc = lrow + (uint32_t)((d0 & 63) * 2);
        *(uint4*)(cbase + (size_t)(d0 >> 6) * CHA + SW128(loc)) = pack8(v);
    }
}

// ================= update =======================================================
__global__ void k_update(float* __restrict__ dout, int iter) {
    int row = blockIdx.x;
    const float* o = g_outp + (size_t)row*OUTD_;
    for (int c = threadIdx.x; c < C_; c += blockDim.x)
        g_preq[row*C_ + c] += o[c];
    if (threadIdx.x == 0) {
        float ny = fminf(fmaxf(g_curr[row*2]   + o[C_],   0.f), 223.f);
        float nx = fminf(fmaxf(g_curr[row*2+1] + o[C_+1], 0.f), 223.f);
        g_curr[row*2]   = ny;
        g_curr[row*2+1] = nx;
        dout[iter*(B_*N_*2) + row*2]     = ny;
        dout[iter*(B_*N_*2) + row*2 + 1] = nx;
    }
}

// ================= launch =======================================================
extern "C" void kernel_launch(void* const* d_in, const int* in_sizes, int n_in,
                              void* d_out, int out_size) {
    (void)in_sizes; (void)n_in; (void)out_size;
    const float* pre_f   = (const float*)d_in[0];
    const float* curr_f  = (const float*)d_in[1];
    const float* first_f = (const float*)d_in[2];
    const int*   prev_b  = (const int*)  d_in[3];
    const int*   first_b = (const int*)  d_in[4];
    const float* lng = (const float*)d_in[5];
    const float* lnb = (const float*)d_in[6];
    const float* ipw = (const float*)d_in[7];
    const float* ipb = (const float*)d_in[8];
    const float* opw = (const float*)d_in[9];
    const float* opb = (const float*)d_in[10];
    const float* n1g = (const float*)d_in[11];
    const float* n1b = (const float*)d_in[12];
    const float* l1w = (const float*)d_in[13];
    const float* l1b = (const float*)d_in[14];
    const float* l2w = (const float*)d_in[15];
    const float* l2b = (const float*)d_in[16];
    const float* n2g = (const float*)d_in[17];
    const float* n2b = (const float*)d_in[18];
    const float* ow  = (const float*)d_in[19];
    const float* ob  = (const float*)d_in[20];

    cudaFuncSetAttribute(k_gemm, cudaFuncAttributeMaxDynamicSharedMemorySize, GEMM_SMEM);

    __nv_bfloat16 *p_ipw, *p_opw, *p_l1w, *p_l2w, *p_oww;
    cudaGetSymbolAddress((void**)&p_ipw, g_ipw);
    cudaGetSymbolAddress((void**)&p_opw, g_opw);
    cudaGetSymbolAddress((void**)&p_l1w, g_l1w);
    cudaGetSymbolAddress((void**)&p_l2w, g_l2w);
    cudaGetSymbolAddress((void**)&p_oww, g_oww);

    float *p_tokens, *p_q, *p_k, *p_v, *p_aproj, *p_x, *p_ff, *p_x2, *p_outp;
    cudaGetSymbolAddress((void**)&p_tokens, g_tokens);
    cudaGetSymbolAddress((void**)&p_q,      g_q);
    cudaGetSymbolAddress((void**)&p_k,      g_k);
    cudaGetSymbolAddress((void**)&p_v,      g_v);
    cudaGetSymbolAddress((void**)&p_aproj,  g_aproj);
    cudaGetSymbolAddress((void**)&p_x,      g_x);
    cudaGetSymbolAddress((void**)&p_ff,     g_ff);
    cudaGetSymbolAddress((void**)&p_x2,     g_x2);
    cudaGetSymbolAddress((void**)&p_outp,   g_outp);

    __nv_bfloat16 *p_tokc, *p_avc, *p_xc, *p_hc, *p_x2c;
    cudaGetSymbolAddress((void**)&p_tokc, g_tokc);
    cudaGetSymbolAddress((void**)&p_avc,  g_avc);
    cudaGetSymbolAddress((void**)&p_xc,   g_xc);
    cudaGetSymbolAddress((void**)&p_hc,   g_hc);
    cudaGetSymbolAddress((void**)&p_x2c,  g_x2c);

    k_wconv<<<18688, 128>>>(ipw, opw, l1w, l2w, ow);
    k_gather<<<M_, 256>>>(pre_f, first_f, prev_b, first_b);

    for (int it = 0; it < REFINE_; it++) {
        k_tokens<<<M_, 256>>>(curr_f, lng, lnb);
        k_gemm<<<N64_IP, 256, GEMM_SMEM>>>(p_tokc, p_ipw, KS_D, N64_IP, ipb,
                                           nullptr, 0, nullptr, TD_, 2, p_q, p_k, p_v);
        k_attn2<<<M_, 256>>>();
        k_gemm<<<N64_OP, 256, GEMM_SMEM>>>(p_avc, p_opw, KS_D, N64_OP, opb,
                                           p_aproj, KP, nullptr, D_, 0,
                                           nullptr, nullptr, nullptr);
        k_ln<<<M_, 256>>>(p_tokens, p_aproj, n1g, n1b, p_x, p_xc);
        k_gemm<<<N64_L1, 256, GEMM_SMEM>>>(p_xc, p_l1w, KS_D, N64_L1, l1b,
                                           nullptr, 0, p_hc, DFF_, 1,
                                           nullptr, nullptr, nullptr);
        k_gemm<<<N64_L2, 256, GEMM_SMEM>>>(p_hc, p_l2w, KS_F, N64_L2, l2b,
                                           p_ff, KP, nullptr, D_, 0,
                                           nullptr, nullptr, nullptr);
        k_ln<<<M_, 256>>>(p_x, p_ff, n2g, n2b, p_x2, p_x2c);
        k_gemm<<<N64_OW, 256, GEMM_SMEM>>>(p_x2c, p_oww, KS_D, N64_OW, ob,
                                           p_outp, OUTD_, nullptr, OUTD_, 0,
                                           nullptr, nullptr, nullptr);
        k_update<<<M_, 256>>>((float*)d_out, it);
    }
}

// round 11
// speedup vs baseline: 11.0823x; 1.2047x over previous
#include <cuda_runtime.h>
#include <cuda_bf16.h>
#include <math.h>
#include <stdint.h>

#define B_    2
#define C_    1024
#define N_    80
#define D_    3074
#define KP    3200      // padded K (50 chunks of 64; even for 128-wide stages)
#define TD_   9222
#define DFF_  2048
#define OUTD_ 1026
#define M_    160
#define REFINE_ 3

#define KC_D   50
#define KC_F   32
#define KS_D   25       // 128-wide stages
#define KS_F   16
#define CHA    20480    // A chunk bytes  (160*128)
#define CHW    8192     // W chunk bytes  (64*128)
#define N64_IP 145
#define N64_OP 49
#define N64_L1 32
#define N64_L2 49
#define N64_OW 17

#define S_OP 3
#define S_L1 4
#define S_L2 3
#define S_OW 8
#define PW_D  3136      // partial width for op/l2 (49*64)
#define PW_L1 2048
#define PW_OW 1088      // 17*64

// ---------------- chunked+swizzled bf16 weights --------------------------------
__device__ __nv_bfloat16 g_ipw[(size_t)KC_D*N64_IP*4096];
__device__ __nv_bfloat16 g_opw[(size_t)KC_D*N64_OP*4096];
__device__ __nv_bfloat16 g_l1w[(size_t)KC_D*N64_L1*4096];
__device__ __nv_bfloat16 g_l2w[(size_t)KC_F*N64_L2*4096];
__device__ __nv_bfloat16 g_oww[(size_t)KC_D*N64_OW*4096];

// ---------------- chunked+swizzled bf16 activations (GEMM A-side) --------------
__device__ __nv_bfloat16 g_tokc[(size_t)KC_D*10240];
__device__ __nv_bfloat16 g_avc [(size_t)KC_D*10240];
__device__ __nv_bfloat16 g_xc  [(size_t)KC_D*10240];
__device__ __nv_bfloat16 g_hc  [(size_t)KC_F*10240];
__device__ __nv_bfloat16 g_x2c [(size_t)KC_D*10240];

// ---------------- fp32 linear activations + split-K partials -------------------
__device__ float g_preq  [M_*C_];
__device__ float g_firstq[M_*C_];
__device__ float g_curr  [M_*2];
__device__ float g_tokens[M_*KP];
__device__ float g_q     [M_*KP];
__device__ float g_k     [M_*KP];
__device__ float g_v     [M_*KP];
__device__ float g_x     [M_*KP];
__device__ float g_partD [(size_t)S_OP*M_*PW_D];   // op / l2 partials (S<=3)
__device__ float g_partH [(size_t)S_L1*M_*PW_L1];  // l1 partials
__device__ float g_partO [(size_t)S_OW*M_*PW_OW];  // ow partials

// ================= helpers =======================================================
__device__ __forceinline__ uint32_t smem_u32(const void* p) {
    uint32_t a;
    asm("{ .reg .u64 t; cvta.to.shared.u64 t, %1; cvt.u32.u64 %0, t; }" : "=r"(a) : "l"(p));
    return a;
}

#define SW128(bo) ((bo) ^ (((bo) >> 3) & 0x70))

__device__ __forceinline__ void mbar_init(uint32_t mbar, uint32_t cnt) {
    asm volatile("mbarrier.init.shared.b64 [%0], %1;" :: "r"(mbar), "r"(cnt) : "memory");
}
__device__ __forceinline__ void mbar_expect(uint32_t mbar, uint32_t bytes) {
    asm volatile("mbarrier.arrive.expect_tx.shared.b64 _, [%0], %1;"
                 :: "r"(mbar), "r"(bytes) : "memory");
}
__device__ __forceinline__ void mbar_wait(uint32_t mbar, uint32_t parity) {
    asm volatile(
        "{\n\t"
        ".reg .pred P1;\n\t"
        "LAB_%=:\n\t"
        "mbarrier.try_wait.parity.acquire.cta.shared::cta.b64 P1, [%0], %1, 0x989680;\n\t"
        "@P1 bra.uni DONE_%=;\n\t"
        "bra.uni LAB_%=;\n\t"
        "DONE_%=:\n\t"
        "}"
        :: "r"(mbar), "r"(parity) : "memory");
}
__device__ __forceinline__ void fence_async() {
    asm volatile("fence.proxy.async.shared::cta;" ::: "memory");
}
__device__ __forceinline__ void bulk_ld(uint32_t dst, const void* src, uint32_t bytes, uint32_t bar) {
    asm volatile(
        "cp.async.bulk.shared::cluster.global.mbarrier::complete_tx::bytes [%0], [%1], %2, [%3];"
        :: "r"(dst), "l"(src), "r"(bytes), "r"(bar) : "memory");
}
__device__ __forceinline__ void ldsm4(uint32_t* r, uint32_t addr) {
    asm volatile("ldmatrix.sync.aligned.m8n8.x4.shared.b16 {%0,%1,%2,%3}, [%4];"
                 : "=r"(r[0]), "=r"(r[1]), "=r"(r[2]), "=r"(r[3]) : "r"(addr));
}
__device__ __forceinline__ void mma16816(float c[4], const uint32_t a[4],
                                         uint32_t b0, uint32_t b1) {
    asm volatile(
        "mma.sync.aligned.m16n8k16.row.col.f32.bf16.bf16.f32 "
        "{%0,%1,%2,%3},{%4,%5,%6,%7},{%8,%9},{%0,%1,%2,%3};"
        : "+f"(c[0]), "+f"(c[1]), "+f"(c[2]), "+f"(c[3])
        : "r"(a[0]), "r"(a[1]), "r"(a[2]), "r"(a[3]), "r"(b0), "r"(b1));
}

// ================= bilinear sampling ============================================
struct Bil { int i0,i1,j0,j1; float w00,w01,w10,w11; };

__device__ __forceinline__ Bil make_bil(int py, int px) {
    float cy = ((float)py + 0.5f) * (14.0f/224.0f) - 0.5f;
    float cx = ((float)px + 0.5f) * (14.0f/224.0f) - 0.5f;
    float fy = floorf(cy), fx = floorf(cx);
    float ay = cy - fy,    ax = cx - fx;
    int y0 = (int)fy, x0 = (int)fx;
    Bil b;
    b.i0 = min(13, max(0, y0));   b.i1 = min(13, max(0, y0+1));
    b.j0 = min(13, max(0, x0));   b.j1 = min(13, max(0, x0+1));
    b.w00 = (1.f-ay)*(1.f-ax); b.w01 = (1.f-ay)*ax;
    b.w10 = ay*(1.f-ax);       b.w11 = ay*ax;
    return b;
}

__device__ __forceinline__ float bil_sample(const float* __restrict__ f, int c, const Bil& b) {
    const float* p = f + c*196;
    return b.w00*p[b.i0*14 + b.j0] + b.w01*p[b.i0*14 + b.j1]
         + b.w10*p[b.i1*14 + b.j0] + b.w11*p[b.i1*14 + b.j1];
}

__device__ __forceinline__ uint4 pack8(const float* v) {
    uint4 r;
    __nv_bfloat162 b0 = __float22bfloat162_rn(make_float2(v[0], v[1]));
    __nv_bfloat162 b1 = __float22bfloat162_rn(make_float2(v[2], v[3]));
    __nv_bfloat162 b2 = __float22bfloat162_rn(make_float2(v[4], v[5]));
    __nv_bfloat162 b3 = __float22bfloat162_rn(make_float2(v[6], v[7]));
    r.x = *(uint32_t*)&b0; r.y = *(uint32_t*)&b1;
    r.z = *(uint32_t*)&b2; r.w = *(uint32_t*)&b3;
    return r;
}

// ================= weight conversion ============================================
__global__ void k_wconv(const float* __restrict__ ipw, const float* __restrict__ opw,
                        const float* __restrict__ l1w, const float* __restrict__ l2w,
                        const float* __restrict__ oww) {
    int b = blockIdx.x;
    const float* src; __nv_bfloat16* dst;
    int N, K, KC, N64, n;
    if (b < 9280)       { n = b;         src = ipw; dst = g_ipw; N = TD_;  K = D_;   KC = KC_D; N64 = N64_IP; }
    else if (b < 12416) { n = b - 9280;  src = opw; dst = g_opw; N = D_;   K = D_;   KC = KC_D; N64 = N64_OP; }
    else if (b < 14464) { n = b - 12416; src = l1w; dst = g_l1w; N = DFF_; K = D_;   KC = KC_D; N64 = N64_L1; }
    else if (b < 17600) { n = b - 14464; src = l2w; dst = g_l2w; N = D_;   K = DFF_; KC = KC_F; N64 = N64_L2; }
    else                { n = b - 17600; src = oww; dst = g_oww; N = OUTD_;K = D_;   KC = KC_D; N64 = N64_OW; }

    bool nok = n < N;
    const float* srow = src + (size_t)n * K;
    char* dbase = (char*)dst + (size_t)(n >> 6) * CHW;
    uint32_t lrow = (uint32_t)((n & 63) * 128);
    size_t kstride = (size_t)N64 * CHW;
    int units = KC * 8;

    for (int u = threadIdx.x; u < units; u += 128) {
        int k0 = u * 8;
        float v[8];
        if (nok && k0 + 8 <= K) {
            float2 f0 = *(const float2*)(srow + k0);
            float2 f1 = *(const float2*)(srow + k0 + 2);
            float2 f2 = *(const float2*)(srow + k0 + 4);
            float2 f3 = *(const float2*)(srow + k0 + 6);
            v[0]=f0.x; v[1]=f0.y; v[2]=f1.x; v[3]=f1.y;
            v[4]=f2.x; v[5]=f2.y; v[6]=f3.x; v[7]=f3.y;
        } else {
            #pragma unroll
            for (int e = 0; e < 8; e++)
                v[e] = (nok && (k0 + e) < K) ? srow[k0 + e] : 0.f;
        }
        uint32_t loc = lrow + (uint32_t)((k0 & 63) * 2);
        *(uint4*)(dbase + (size_t)(k0 >> 6) * kstride + SW128(loc)) = pack8(v);
    }
}

// ================= gather (align inline) ========================================
__global__ void k_gather(const float* __restrict__ pre_f,
                         const float* __restrict__ first_f,
                         const int* __restrict__ prev,
                         const int* __restrict__ first) {
    int row = blockIdx.x;
    int b = row / N_, j = row % N_;
    __shared__ int sp[N_*2], sf[N_*2];
    __shared__ int skey[256];
    int t = threadIdx.x;
    for (int i = t; i < N_*2; i += 256) {
        sp[i] = prev [b*N_*2 + i];
        sf[i] = first[b*N_*2 + i];
    }
    __syncthreads();
    int key = 0x7FFFFFFF;
    if (t < N_) {
        int acc = 0;
        for (int q = 0; q < N_; q++) {
            int qq = (q - t + N_) % N_;
            acc += abs(sp[q*2]   - sf[qq*2]);
            acc += abs(sp[q*2+1] - sf[qq*2+1]);
        }
        key = acc * 128 + t;
    }
    skey[t] = key; __syncthreads();
    for (int s = 128; s >= 1; s >>= 1) {
        if (t < s) skey[t] = min(skey[t], skey[t+s]);
        __syncthreads();
    }
    int best = skey[0] & 127;

    int jj = (j - best + N_) % N_;
    int py = sp[j*2], px = sp[j*2+1];
    Bil bp = make_bil(py, px);
    Bil bf = make_bil(sf[jj*2], sf[jj*2+1]);
    const float* pf = pre_f   + b*C_*196;
    const float* ff = first_f + b*C_*196;
    for (int c = t; c < C_; c += 256) {
        g_preq  [row*C_ + c] = bil_sample(pf, c, bp);
        g_firstq[row*C_ + c] = bil_sample(ff, c, bf);
    }
    if (t < KP - D_) {
        g_q[(size_t)row*KP + D_ + t] = 0.f;
        g_k[(size_t)row*KP + D_ + t] = 0.f;
        g_v[(size_t)row*KP + D_ + t] = 0.f;
    }
    if (t == 0) {
        g_curr[row*2]   = (float)py;
        g_curr[row*2+1] = (float)px;
    }
}

// ================= tokens = LN(concat) + pe(inline) =============================
__global__ void k_tokens(const float* __restrict__ curr_f,
                         const float* __restrict__ lng,
                         const float* __restrict__ lnb) {
    int row = blockIdx.x;
    int b = row / N_, n = row % N_;
    __shared__ float srow[D_];
    __shared__ float red[256];
    int t = threadIdx.x;

    float cy = g_curr[row*2], cx = g_curr[row*2+1];
    int py = (int)cy, px = (int)cx;
    Bil bb = make_bil(py, px);
    const float* cf = curr_f + b*C_*196;

    float lsum = 0.f;
    for (int d = t; d < D_; d += 256) {
        float v;
        if      (d < C_)        v = g_preq[row*C_ + d];
        else if (d < 2*C_)      v = bil_sample(cf, d - C_, bb);
        else if (d == 2*C_)     v = cy;
        else if (d == 2*C_+1)   v = cx;
        else                    v = g_firstq[row*C_ + (d - (2*C_+2))];
        srow[d] = v;
        lsum += v;
    }
    red[t] = lsum; __syncthreads();
    for (int s = 128; s >= 1; s >>= 1) { if (t < s) red[t] += red[t+s]; __syncthreads(); }
    float mean = red[0] * (1.f/(float)D_);
    __syncthreads();

    float lsq = 0.f;
    for (int d = t; d < D_; d += 256) { float u = srow[d] - mean; lsq += u*u; }
    red[t] = lsq; __syncthreads();
    for (int s = 128; s >= 1; s >>= 1) { if (t < s) red[t] += red[t+s]; __syncthreads(); }
    float rstd = rsqrtf(red[0] * (1.f/(float)D_) + 1e-5f);
    __syncthreads();

    char* cbase = (char*)g_tokc;
    uint32_t lrow = (uint32_t)(row * 128);
    for (int u = t; u < KP/8; u += 256) {
        int d0 = u * 8;
        float v[8];
        #pragma unroll
        for (int e = 0; e < 8; e++) {
            int d = d0 + e;
            float pe = 0.f;
            if (d < D_) {
                int k2 = d & ~1;
                float div = expf((float)k2 * (-9.210340371976184f / (float)D_));
                float arg = (float)n * div;
                pe = (d & 1) ? cosf(arg) : sinf(arg);
            }
            v[e] = (d < D_) ? (lng[d] * ((srow[d] - mean) * rstd) + lnb[d] + pe) : 0.f;
        }
        float4* fp = (float4*)&g_tokens[(size_t)row*KP + d0];
        fp[0] = make_float4(v[0], v[1], v[2], v[3]);
        fp[1] = make_float4(v[4], v[5], v[6], v[7]);
        uint32_t loc = lrow + (uint32_t)((d0 & 63) * 2);
        *(uint4*)(cbase + (size_t)(d0 >> 6) * CHA + SW128(loc)) = pack8(v);
    }
}

// ================= GEMM: split-K, 128-wide stages ===============================
// grid = (N64, S). mode 2: qkv split fp32; mode 3: fp32 partial (no bias) to
// OutF + z*160*ldo.
#define NSTG 3
#define STAGE_B (2*CHA + 2*CHW)              // 57344
#define GEMM_SMEM (NSTG*STAGE_B + 64)        // 172096

__global__ __launch_bounds__(256) void k_gemm(
    const __nv_bfloat16* __restrict__ Ac,
    const __nv_bfloat16* __restrict__ Wc,
    int KS, int N64,
    const float* __restrict__ bias,
    float* __restrict__ OutF, int ldo,
    int mode,
    float* __restrict__ oq, float* __restrict__ okk, float* __restrict__ ov)
{
    extern __shared__ char sm[];
    uint32_t smb = smem_u32(sm);
    uint32_t mb = smb + NSTG * STAGE_B;

    int t = threadIdx.x;
    int warp = t >> 5, lane = t & 31;
    int wm = (warp >> 2) * 80;
    int wn = (warp & 3) * 16;
    int qr = lane >> 2, qc2 = (lane & 3) * 2;
    int nb = blockIdx.x, n0 = nb * 64;
    int z = blockIdx.y, S = gridDim.y;
    int ks0 = (KS * z) / S, ks1 = (KS * (z + 1)) / S;
    int nst = ks1 - ks0;

    int sub   = lane & 7;
    int m_off = ((lane >> 3) & 1) * 8 + sub;
    int k_off = (lane >> 4) * 8;
    uint32_t swz = (uint32_t)(sub * 16);
    uint32_t w_row_off = (uint32_t)((wn + m_off) * 128);

    if (t == 0) {
        mbar_init(mb, 1); mbar_init(mb + 8, 1); mbar_init(mb + 16, 1);
        fence_async();
    }
    __syncthreads();

    float acc[5][2][4];
    #pragma unroll
    for (int i = 0; i < 5; i++)
        #pragma unroll
        for (int j = 0; j < 2; j++)
            #pragma unroll
            for (int r = 0; r < 4; r++) acc[i][j][r] = 0.f;

    if (t == 0) {
        #pragma unroll
        for (int p = 0; p < 2; p++) {
            if (p >= nst) break;
            int kg = ks0 + p;
            uint32_t s = p, bar = mb + s*8;
            mbar_expect(bar, STAGE_B);
            bulk_ld(smb + s*STAGE_B, (const char*)Ac + (size_t)(2*kg)*CHA, 2*CHA, bar);
            bulk_ld(smb + s*STAGE_B + 2*CHA,
                    (const char*)Wc + ((size_t)(2*kg)*N64 + nb)*CHW, CHW, bar);
            bulk_ld(smb + s*STAGE_B + 2*CHA + CHW,
                    (const char*)Wc + ((size_t)(2*kg+1)*N64 + nb)*CHW, CHW, bar);
        }
    }

    uint32_t amA[5][4], bmA[4], amB[5][4], bmB[4];

    for (int l = 0; l < nst; l++) {
        int s = l % NSTG;
        mbar_wait(mb + s*8, (uint32_t)((l/NSTG) & 1));
        if (t == 0 && l + 2 < nst) {
            int l2i = l + 2;
            int kg = ks0 + l2i;
            uint32_t s2 = l2i % NSTG, bar = mb + s2*8;
            mbar_expect(bar, STAGE_B);
            bulk_ld(smb + s2*STAGE_B, (const char*)Ac + (size_t)(2*kg)*CHA, 2*CHA, bar);
            bulk_ld(smb + s2*STAGE_B + 2*CHA,
                    (const char*)Wc + ((size_t)(2*kg)*N64 + nb)*CHW, CHW, bar);
            bulk_ld(smb + s2*STAGE_B + 2*CHA + CHW,
                    (const char*)Wc + ((size_t)(2*kg+1)*N64 + nb)*CHW, CHW, bar);
        }
        uint32_t st_b = smb + s*STAGE_B;

        #define LDP(BUFam, BUFbm, p) do { \
            int c2_ = (p) >> 2, kk_ = ((p) & 3) * 16; \
            uint32_t as_ = st_b + (uint32_t)(c2_ * CHA); \
            uint32_t ws_ = st_b + (uint32_t)(2*CHA + c2_ * CHW); \
            uint32_t col_ = ((uint32_t)((kk_ + k_off) * 2)) ^ swz; \
            ldsm4(BUFam[0], as_ + (uint32_t)((wm +   0 + m_off) * 128) + col_); \
            ldsm4(BUFam[1], as_ + (uint32_t)((wm +  16 + m_off) * 128) + col_); \
            ldsm4(BUFam[2], as_ + (uint32_t)((wm +  32 + m_off) * 128) + col_); \
            ldsm4(BUFam[3], as_ + (uint32_t)((wm +  48 + m_off) * 128) + col_); \
            ldsm4(BUFam[4], as_ + (uint32_t)((wm +  64 + m_off) * 128) + col_); \
            ldsm4(BUFbm,    ws_ + w_row_off + col_); \
        } while (0)

        #define MMAP(BUFam, BUFbm) do { \
            _Pragma("unroll") \
            for (int i_ = 0; i_ < 5; i_++) { \
                mma16816(acc[i_][0], BUFam[i_], BUFbm[0], BUFbm[2]); \
                mma16816(acc[i_][1], BUFam[i_], BUFbm[1], BUFbm[3]); \
            } \
        } while (0)

        LDP(amA, bmA, 0);
        #pragma unroll
        for (int p = 0; p < 8; p += 2) {
            if (p + 1 < 8) LDP(amB, bmB, p + 1);
            MMAP(amA, bmA);
            if (p + 2 < 8) LDP(amA, bmA, p + 2);
            MMAP(amB, bmB);
        }
        #undef LDP
        #undef MMAP
        __syncthreads();
    }

    // ---- epilogue ----
    if (mode == 3) {
        float* dst = OutF + (size_t)z * M_ * ldo;
        #pragma unroll
        for (int i = 0; i < 5; i++) {
            #pragma unroll
            for (int j = 0; j < 2; j++) {
                int n = n0 + wn + j*8 + qc2;
                #pragma unroll
                for (int h = 0; h < 2; h++) {
                    int m = wm + i*16 + qr + h*8;
                    dst[(size_t)m * ldo + n]     = acc[i][j][h*2 + 0];
                    dst[(size_t)m * ldo + n + 1] = acc[i][j][h*2 + 1];
                }
            }
        }
    } else {  // mode 2: qkv split
        #pragma unroll
        for (int i = 0; i < 5; i++) {
            #pragma unroll
            for (int j = 0; j < 2; j++) {
                int n = n0 + wn + j*8 + qc2;
                #pragma unroll
                for (int h = 0; h < 2; h++) {
                    int m = wm + i*16 + qr + h*8;
                    #pragma unroll
                    for (int c2 = 0; c2 < 2; c2++) {
                        int nn = n + c2;
                        if (nn >= TD_) continue;
                        float v = acc[i][j][h*2 + c2] + __ldg(&bias[nn]);
                        int seg = (nn >= 6148) ? 2 : (nn >= 3074 ? 1 : 0);
                        int col = nn - seg * 3074;
                        float* dstq = (seg == 0) ? oq : (seg == 1 ? okk : ov);
                        dstq[(size_t)m * KP + col] = v;
                    }
                }
            }
        }
    }
}

// ================= attention: one q-row per block ================================
__global__ __launch_bounds__(256) void k_attn2() {
    int r = blockIdx.x;
    int b = r / N_;
    int t = threadIdx.x, w = t >> 5, lane = t & 31;
    __shared__ float qs[KP];
    __shared__ float sc[N_];

    float4* qs4 = (float4*)qs;
    const float4* qp = (const float4*)&g_q[(size_t)r*KP];
    for (int u = t; u < KP/4; u += 256) qs4[u] = qp[u];
    __syncthreads();

    float scale = rsqrtf((float)D_);
    for (int kn = w; kn < N_; kn += 8) {
        const float4* kp = (const float4*)&g_k[(size_t)(b*N_ + kn)*KP];
        float acc = 0.f;
        for (int u = lane; u < KP/4; u += 32) {
            float4 a = qs4[u], c = kp[u];
            acc += a.x*c.x + a.y*c.y + a.z*c.z + a.w*c.w;
        }
        #pragma unroll
        for (int o = 16; o > 0; o >>= 1) acc += __shfl_down_sync(0xffffffffu, acc, o);
        if (lane == 0) sc[kn] = acc * scale;
    }
    __syncthreads();

    if (w == 0) {
        float v0 = (lane      < N_) ? sc[lane]      : -1e30f;
        float v1 = (lane + 32 < N_) ? sc[lane + 32] : -1e30f;
        float v2 = (lane + 64 < N_) ? sc[lane + 64] : -1e30f;
        float mx = fmaxf(v0, fmaxf(v1, v2));
        #pragma unroll
        for (int o = 16; o > 0; o >>= 1) mx = fmaxf(mx, __shfl_xor_sync(0xffffffffu, mx, o));
        float e0 = (lane      < N_) ? expf(v0 - mx) : 0.f;
        float e1 = (lane + 32 < N_) ? expf(v1 - mx) : 0.f;
        float e2 = (lane + 64 < N_) ? expf(v2 - mx) : 0.f;
        float s = e0 + e1 + e2;
        #pragma unroll
        for (int o = 16; o > 0; o >>= 1) s += __shfl_xor_sync(0xffffffffu, s, o);
        float inv = 1.f / s;
        if (lane      < N_) sc[lane]      = e0 * inv;
        if (lane + 32 < N_) sc[lane + 32] = e1 * inv;
        if (lane + 64 < N_) sc[lane + 64] = e2 * inv;
    }
    __syncthreads();

    char* cbase = (char*)g_avc;
    uint32_t lrow = (uint32_t)(r * 128);
    const float* vb = &g_v[(size_t)b*N_*KP];
    for (int gidx = t; gidx < KP/8; gidx += 256) {
        int d0 = gidx * 8;
        float a8[8] = {0.f,0.f,0.f,0.f,0.f,0.f,0.f,0.f};
        #pragma unroll 4
        for (int k = 0; k < N_; k++) {
            const float4* vp = (const float4*)(vb + (size_t)k*KP + d0);
            float4 v0 = vp[0], v1 = vp[1];
            float sck = sc[k];
            a8[0] += sck*v0.x; a8[1] += sck*v0.y; a8[2] += sck*v0.z; a8[3] += sck*v0.w;
            a8[4] += sck*v1.x; a8[5] += sck*v1.y; a8[6] += sck*v1.z; a8[7] += sck*v1.w;
        }
        uint32_t loc = lrow + (uint32_t)((d0 & 63) * 2);
        *(uint4*)(cbase + (size_t)(d0 >> 6) * CHA + SW128(loc)) = pack8(a8);
    }
}

// ================= layernorm: LN(in0 + Σ partials + pbias) ======================
__global__ void k_ln(const float* __restrict__ in0,
                     const float* __restrict__ part, int partW, int S,
                     const float* __restrict__ pbias,
                     const float* __restrict__ g, const float* __restrict__ bta,
                     float* __restrict__ outF, __nv_bfloat16* __restrict__ outC) {
    int row = blockIdx.x;
    __shared__ float srow[D_];
    __shared__ float red[256];
    int t = threadIdx.x;
    float lsum = 0.f;
    for (int d = t; d < D_; d += 256) {
        float v = in0[(size_t)row*KP + d] + pbias[d];
        for (int z = 0; z < S; z++)
            v += part[((size_t)z*M_ + row)*partW + d];
        srow[d] = v; lsum += v;
    }
    red[t] = lsum; __syncthreads();
    for (int s = 128; s >= 1; s >>= 1) { if (t < s) red[t] += red[t+s]; __syncthreads(); }
    float mean = red[0] * (1.f/(float)D_);
    __syncthreads();
    float lsq = 0.f;
    for (int d = t; d < D_; d += 256) { float u = srow[d] - mean; lsq += u*u; }
    red[t] = lsq; __syncthreads();
    for (int s = 128; s >= 1; s >>= 1) { if (t < s) red[t] += red[t+s]; __syncthreads(); }
    float rstd = rsqrtf(red[0] * (1.f/(float)D_) + 1e-5f);
    __syncthreads();

    char* cbase = (char*)outC;
    uint32_t lrow = (uint32_t)(row * 128);
    for (int u = t; u < KP/8; u += 256) {
        int d0 = u * 8;
        float v[8];
        #pragma unroll
        for (int e = 0; e < 8; e++) {
            int d = d0 + e;
            v[e] = (d < D_) ? (g[d] * ((srow[d] - mean) * rstd) + bta[d]) : 0.f;
        }
        float4* fp = (float4*)&outF[(size_t)row*KP + d0];
        fp[0] = make_float4(v[0], v[1], v[2], v[3]);
        fp[1] = make_float4(v[4], v[5], v[6], v[7]);
        uint32_t loc = lrow + (uint32_t)((d0 & 63) * 2);
        *(uint4*)(cbase + (size_t)(d0 >> 6) * CHA + SW128(loc)) = pack8(v);
    }
}

// ================= h = relu(Σ partials + l1b) -> chunked bf16 ====================
__global__ void k_hred(const float* __restrict__ bias) {
    int row = blockIdx.x;
    int t = threadIdx.x;          // 256 threads, 256 units of 8
    int d0 = t * 8;
    float v[8];
    #pragma unroll
    for (int e = 0; e < 8; e++) v[e] = bias[d0 + e];
    #pragma unroll
    for (int z = 0; z < S_L1; z++) {
        const float4* p = (const float4*)&g_partH[((size_t)z*M_ + row)*PW_L1 + d0];
        float4 a = p[0], b = p[1];
        v[0]+=a.x; v[1]+=a.y; v[2]+=a.z; v[3]+=a.w;
        v[4]+=b.x; v[5]+=b.y; v[6]+=b.z; v[7]+=b.w;
    }
    #pragma unroll
    for (int e = 0; e < 8; e++) v[e] = fmaxf(v[e], 0.f);
    uint32_t loc = (uint32_t)(row * 128 + (d0 & 63) * 2);
    *(uint4*)((char*)g_hc + (size_t)(d0 >> 6) * CHA + SW128(loc)) = pack8(v);
}

// ================= update: o = Σ partials + ob ==================================
__global__ void k_update(const float* __restrict__ ob, float* __restrict__ dout, int iter) {
    int row = blockIdx.x;
    int t = threadIdx.x;
    for (int c = t; c < C_; c += 256) {
        float o = ob[c];
        #pragma unroll
        for (int z = 0; z < S_OW; z++)
            o += g_partO[((size_t)z*M_ + row)*PW_OW + c];
        g_preq[row*C_ + c] += o;
    }
    if (t == 0) {
        float oy = ob[C_], ox = ob[C_ + 1];
        #pragma unroll
        for (int z = 0; z < S_OW; z++) {
            oy += g_partO[((size_t)z*M_ + row)*PW_OW + C_];
            ox += g_partO[((size_t)z*M_ + row)*PW_OW + C_ + 1];
        }
        float ny = fminf(fmaxf(g_curr[row*2]   + oy, 0.f), 223.f);
        float nx = fminf(fmaxf(g_curr[row*2+1] + ox, 0.f), 223.f);
        g_curr[row*2]   = ny;
        g_curr[row*2+1] = nx;
        dout[iter*(B_*N_*2) + row*2]     = ny;
        dout[iter*(B_*N_*2) + row*2 + 1] = nx;
    }
}

// ================= launch =======================================================
extern "C" void kernel_launch(void* const* d_in, const int* in_sizes, int n_in,
                              void* d_out, int out_size) {
    (void)in_sizes; (void)n_in; (void)out_size;
    const float* pre_f   = (const float*)d_in[0];
    const float* curr_f  = (const float*)d_in[1];
    const float* first_f = (const float*)d_in[2];
    const int*   prev_b  = (const int*)  d_in[3];
    const int*   first_b = (const int*)  d_in[4];
    const float* lng = (const float*)d_in[5];
    const float* lnb = (const float*)d_in[6];
    const float* ipw = (const float*)d_in[7];
    const float* ipb = (const float*)d_in[8];
    const float* opw = (const float*)d_in[9];
    const float* opb = (const float*)d_in[10];
    const float* n1g = (const float*)d_in[11];
    const float* n1b = (const float*)d_in[12];
    const float* l1w = (const float*)d_in[13];
    const float* l1b = (const float*)d_in[14];
    const float* l2w = (const float*)d_in[15];
    const float* l2b = (const float*)d_in[16];
    const float* n2g = (const float*)d_in[17];
    const float* n2b = (const float*)d_in[18];
    const float* ow  = (const float*)d_in[19];
    const float* ob  = (const float*)d_in[20];

    cudaFuncSetAttribute(k_gemm, cudaFuncAttributeMaxDynamicSharedMemorySize, GEMM_SMEM);

    __nv_bfloat16 *p_ipw, *p_opw, *p_l1w, *p_l2w, *p_oww;
    cudaGetSymbolAddress((void**)&p_ipw, g_ipw);
    cudaGetSymbolAddress((void**)&p_opw, g_opw);
    cudaGetSymbolAddress((void**)&p_l1w, g_l1w);
    cudaGetSymbolAddress((void**)&p_l2w, g_l2w);
    cudaGetSymbolAddress((void**)&p_oww, g_oww);

    float *p_tokens, *p_q, *p_k, *p_v, *p_x, *p_partD, *p_partH, *p_partO;
    cudaGetSymbolAddress((void**)&p_tokens, g_tokens);
    cudaGetSymbolAddress((void**)&p_q,      g_q);
    cudaGetSymbolAddress((void**)&p_k,      g_k);
    cudaGetSymbolAddress((void**)&p_v,      g_v);
    cudaGetSymbolAddress((void**)&p_x,      g_x);
    cudaGetSymbolAddress((void**)&p_partD,  g_partD);
    cudaGetSymbolAddress((void**)&p_partH,  g_partH);
    cudaGetSymbolAddress((void**)&p_partO,  g_partO);

    __nv_bfloat16 *p_tokc, *p_avc, *p_xc, *p_hc, *p_x2c;
    cudaGetSymbolAddress((void**)&p_tokc, g_tokc);
    cudaGetSymbolAddress((void**)&p_avc,  g_avc);
    cudaGetSymbolAddress((void**)&p_xc,   g_xc);
    cudaGetSymbolAddress((void**)&p_hc,   g_hc);
    cudaGetSymbolAddress((void**)&p_x2c,  g_x2c);

    k_wconv<<<18688, 128>>>(ipw, opw, l1w, l2w, ow);
    k_gather<<<M_, 256>>>(pre_f, first_f, prev_b, first_b);

    dim3 gip(N64_IP, 1);
    dim3 gop(N64_OP, S_OP);
    dim3 gl1(N64_L1, S_L1);
    dim3 gl2(N64_L2, S_L2);
    dim3 gow(N64_OW, S_OW);

    for (int it = 0; it < REFINE_; it++) {
        k_tokens<<<M_, 256>>>(curr_f, lng, lnb);
        k_gemm<<<gip, 256, GEMM_SMEM>>>(p_tokc, p_ipw, KS_D, N64_IP, ipb,
                                        nullptr, 0, 2, p_q, p_k, p_v);
        k_attn2<<<M_, 256>>>();
        k_gemm<<<gop, 256, GEMM_SMEM>>>(p_avc, p_opw, KS_D, N64_OP, nullptr,
                                        p_partD, PW_D, 3, nullptr, nullptr, nullptr);
        k_ln<<<M_, 256>>>(p_tokens, p_partD, PW_D, S_OP, opb,
                          n1g, n1b, p_x, p_xc);
        k_gemm<<<gl1, 256, GEMM_SMEM>>>(p_xc, p_l1w, KS_D, N64_L1, nullptr,
                                        p_partH, PW_L1, 3, nullptr, nullptr, nullptr);
        k_hred<<<M_, 256>>>(l1b);
        k_gemm<<<gl2, 256, GEMM_SMEM>>>(p_hc, p_l2w, KS_F, N64_L2, nullptr,
                                        p_partD, PW_D, 3, nullptr, nullptr, nullptr);
        k_ln<<<M_, 256>>>(p_x, p_partD, PW_D, S_L2, l2b,
                          n2g, n2b, p_x, p_x2c);
        k_gemm<<<gow, 256, GEMM_SMEM>>>(p_x2c, p_oww, KS_D, N64_OW, nullptr,
                                        p_partO, PW_OW, 3, nullptr, nullptr, nullptr);
        k_update<<<M_, 256>>>(ob, (float*)d_out, it);
    }
}